// round 12
// baseline (speedup 1.0000x reference)
#include <cuda_runtime.h>
#include <cuda_fp16.h>
#include <math.h>
#include <stdint.h>

// ---------------------------------------------------------------------------
// Problem dims (fixed by the reference)
// ---------------------------------------------------------------------------
#define SEQ    2048
#define BATCH  32
#define DIM    1024
#define M_TOT  (SEQ * BATCH)     // 65536
#define N_TOT  (3 * DIM)         // 3072
#define K_TOT  DIM               // 1024

// GEMM tile: 128-thread CTAs (4 warps, 64x64 warp tiles), 2 CTAs/SM
#define BM 128
#define BN 128
#define BK 32
#define NCHUNK (K_TOT / BK)      // 32
#define NSTAGE 3
#define ASTRIDE 36               // floats per SMEM row (32 + 4 pad): LDS banks
                                 // (36q + r)%32 = (4q+r)%32 all-distinct

// SMEM layout (bytes)
#define A_STG_BYTES (BM * ASTRIDE * 4)          // 18432
#define B_STG_BYTES (BN * ASTRIDE * 4)          // 18432
#define SMEM_B_BASE (NSTAGE * A_STG_BYTES)      // 55296
#define SMEM_BYTES  (SMEM_B_BASE + NSTAGE * B_STG_BYTES)  // 110592

// Scan chunking: 32 chunks of 64 steps; 8 features per thread (uint4 loads)
#define NCHK    32
#define CHKLEN  (SEQ / NCHK)      // 64
#define NCH8    (BATCH * DIM / 8) // 4096 chains-of-8

// Scratch (device globals; no cudaMalloc allowed)
__device__ __half g_act[(size_t)M_TOT * N_TOT];      // 384 MB fp16 gates
__device__ float  g_A [(size_t)NCHK * BATCH * DIM];  // per-chunk A = prod f
__device__ float  g_B [(size_t)NCHK * BATCH * DIM];  // per-chunk B
__device__ float  g_h0[(size_t)NCHK * BATCH * DIM];  // chunk entry states

// ---------------------------------------------------------------------------
// Helpers
// ---------------------------------------------------------------------------
__device__ __forceinline__ uint32_t smem_u32(const void* p) {
    uint32_t a;
    asm("{ .reg .u64 t; cvta.to.shared.u64 t, %1; cvt.u32.u64 %0, t; }"
        : "=r"(a) : "l"(p));
    return a;
}
__device__ __forceinline__ uint32_t tf32_rna(float x) {
    uint32_t r; asm("cvt.rna.tf32.f32 %0, %1;" : "=r"(r) : "f"(x)); return r;
}
__device__ __forceinline__ float rcp_fast(float x) {
    float r; asm("rcp.approx.f32 %0, %1;" : "=f"(r) : "f"(x)); return r;
}
__device__ __forceinline__ float sigmoid_f(float x) {
    return rcp_fast(1.0f + __expf(-x));
}
__device__ __forceinline__ float tanh_f(float x) {
    return 1.0f - 2.0f * rcp_fast(1.0f + __expf(2.0f * x));
}

__device__ __forceinline__ void cp_async16(uint32_t dst_smem, const void* src) {
    asm volatile("cp.async.cg.shared.global [%0], [%1], 16;"
                 :: "r"(dst_smem), "l"(src) : "memory");
}
__device__ __forceinline__ void cp_commit() {
    asm volatile("cp.async.commit_group;" ::: "memory");
}
template <int N>
__device__ __forceinline__ void cp_wait() {
    asm volatile("cp.async.wait_group %0;" :: "n"(N) : "memory");
}

// m16n8k8 tf32 HMMA (portable PTX, legal at compute_103)
__device__ __forceinline__ void mma_tf32(float* d,
                                         const uint32_t* a,
                                         const uint32_t* bb) {
    asm volatile(
        "mma.sync.aligned.m16n8k8.row.col.f32.tf32.tf32.f32 "
        "{%0,%1,%2,%3}, {%4,%5,%6,%7}, {%8,%9}, {%0,%1,%2,%3};\n"
        : "+f"(d[0]), "+f"(d[1]), "+f"(d[2]), "+f"(d[3])
        : "r"(a[0]), "r"(a[1]), "r"(a[2]), "r"(a[3]),
          "r"(bb[0]), "r"(bb[1]));
}

// ---------------------------------------------------------------------------
// Kernel 1: cp.async 3-stage pipelined tf32 HMMA GEMM.
//   Stages RAW fp32 X/W; fragments are rounded to tf32 (rna) in registers
//   right before the MMA (CVTs hide under the tensor phase on the fma pipe).
//   128 threads = 4 warps in 2(M) x 2(N); warp tile 64x64; 2 CTAs/SM.
//   Epilogue: bias + activation -> fp16 gates.
// ---------------------------------------------------------------------------
__global__ __launch_bounds__(128, 2)
void gemm_hmma_kernel(const float* __restrict__ X,
                      const float* __restrict__ W,
                      const float* __restrict__ b)
{
    extern __shared__ __align__(16) char smem[];
    const uint32_t sbase = smem_u32(smem);

    const int tid = threadIdx.x;
    const int wid = tid >> 5;       // 0..3
    const int lid = tid & 31;
    const int lq  = lid >> 2;       // 0..7
    const int lr  = lid & 3;        // 0..3

    const int wm = (wid >> 1) * 64; // warp M offset: 0 / 64
    const int wn = (wid & 1) * 64;  // warp N offset: 0 / 64

    const int block_m = blockIdx.y * BM;
    const int block_n = blockIdx.x * BN;

    const float* Abase = X + (size_t)block_m * K_TOT;
    const float* Bbase = W + (size_t)block_n * K_TOT;

    float acc[4][8][4];
#pragma unroll
    for (int mt = 0; mt < 4; ++mt)
#pragma unroll
        for (int nt = 0; nt < 8; ++nt)
#pragma unroll
            for (int r = 0; r < 4; ++r) acc[mt][nt][r] = 0.0f;

#pragma unroll
    for (int p = 0; p < NSTAGE; ++p) {
        const int kcol = p * BK;
        const uint32_t a_s = sbase + p * A_STG_BYTES;
        const uint32_t b_s = sbase + SMEM_B_BASE + p * B_STG_BYTES;
#pragma unroll
        for (int i = 0; i < 8; ++i) {
            int pos = tid + i * 128;
            int r = pos >> 3, c4 = pos & 7;
            cp_async16(a_s + (uint32_t)(r * ASTRIDE + c4 * 4) * 4,
                       Abase + (size_t)r * K_TOT + kcol + c4 * 4);
        }
#pragma unroll
        for (int i = 0; i < 8; ++i) {
            int pos = tid + i * 128;
            int r = pos >> 3, c4 = pos & 7;
            cp_async16(b_s + (uint32_t)(r * ASTRIDE + c4 * 4) * 4,
                       Bbase + (size_t)r * K_TOT + kcol + c4 * 4);
        }
        cp_commit();
    }

    for (int c = 0; c < NCHUNK; ++c) {
        const int buf = c % NSTAGE;
        cp_wait<NSTAGE - 1>();
        __syncthreads();

        const float* As = (const float*)(smem + buf * A_STG_BYTES);
        const float* Bs = (const float*)(smem + SMEM_B_BASE + buf * B_STG_BYTES);

#pragma unroll
        for (int ks = 0; ks < 4; ++ks) {
            const int k0 = ks * 8;
            uint32_t afrag[4][4], bfrag[8][2];
#pragma unroll
            for (int mt = 0; mt < 4; ++mt) {
                int base = (wm + mt * 16 + lq) * ASTRIDE + k0 + lr;
                afrag[mt][0] = tf32_rna(As[base]);
                afrag[mt][1] = tf32_rna(As[base + 8 * ASTRIDE]);
                afrag[mt][2] = tf32_rna(As[base + 4]);
                afrag[mt][3] = tf32_rna(As[base + 8 * ASTRIDE + 4]);
            }
#pragma unroll
            for (int nt = 0; nt < 8; ++nt) {
                int base = (wn + nt * 8 + lq) * ASTRIDE + k0 + lr;
                bfrag[nt][0] = tf32_rna(Bs[base]);
                bfrag[nt][1] = tf32_rna(Bs[base + 4]);
            }
#pragma unroll
            for (int mt = 0; mt < 4; ++mt)
#pragma unroll
                for (int nt = 0; nt < 8; ++nt)
                    mma_tf32(acc[mt][nt], afrag[mt], bfrag[nt]);
        }

        __syncthreads();

        if (c + NSTAGE < NCHUNK) {
            const int kcol = (c + NSTAGE) * BK;
            const uint32_t a_s = sbase + buf * A_STG_BYTES;
            const uint32_t b_s = sbase + SMEM_B_BASE + buf * B_STG_BYTES;
#pragma unroll
            for (int i = 0; i < 8; ++i) {
                int pos = tid + i * 128;
                int r = pos >> 3, c4 = pos & 7;
                cp_async16(a_s + (uint32_t)(r * ASTRIDE + c4 * 4) * 4,
                           Abase + (size_t)r * K_TOT + kcol + c4 * 4);
            }
#pragma unroll
            for (int i = 0; i < 8; ++i) {
                int pos = tid + i * 128;
                int r = pos >> 3, c4 = pos & 7;
                cp_async16(b_s + (uint32_t)(r * ASTRIDE + c4 * 4) * 4,
                           Bbase + (size_t)r * K_TOT + kcol + c4 * 4);
            }
        }
        cp_commit();
    }

    // ---- epilogue: bias + activation -> fp16 gates ----
    const bool is_tanh = (block_n < DIM);   // BN=128 divides DIM

#pragma unroll
    for (int nt = 0; nt < 8; ++nt) {
        const int gc = block_n + wn + nt * 8 + 2 * lr;   // even
        const float b0 = __ldg(&b[gc]);
        const float b1 = __ldg(&b[gc + 1]);
#pragma unroll
        for (int mt = 0; mt < 4; ++mt) {
            const int gm0 = block_m + wm + mt * 16 + lq;
            const int gm1 = gm0 + 8;
            float v00 = acc[mt][nt][0] + b0;
            float v01 = acc[mt][nt][1] + b1;
            float v10 = acc[mt][nt][2] + b0;
            float v11 = acc[mt][nt][3] + b1;
            float a00, a01, a10, a11;
            if (is_tanh) {
                a00 = tanh_f(v00); a01 = tanh_f(v01);
                a10 = tanh_f(v10); a11 = tanh_f(v11);
            } else {
                a00 = sigmoid_f(v00); a01 = sigmoid_f(v01);
                a10 = sigmoid_f(v10); a11 = sigmoid_f(v11);
            }
            *(__half2*)(&g_act[(size_t)gm0 * N_TOT + gc]) = __floats2half2_rn(a00, a01);
            *(__half2*)(&g_act[(size_t)gm1 * N_TOT + gc]) = __floats2half2_rn(a10, a11);
        }
    }
}

// ---------------------------------------------------------------------------
// Scan pass 1: per (chunk, 8-feature chain) affine map: h_out = A*h_in + B.
// 131072 threads (32 chunks x 4096 chains) -> ~7 warps/SM, bandwidth-bound.
// ---------------------------------------------------------------------------
__global__ __launch_bounds__(128)
void scan_part1(void)
{
    const int g   = blockIdx.x * 128 + threadIdx.x;   // 0 .. NCHK*NCH8-1
    const int chk = g >> 12;                          // /4096
    const int fc  = g & (NCH8 - 1);                   // chain-of-8 index
    const int bb  = fc >> 7;                          // batch
    const int dh  = fc & 127;                         // 8-feature group in DIM

    const uint4* __restrict__ act8 = (const uint4*)g_act;  // 8 halves per uint4

    float A[8], B[8];
#pragma unroll
    for (int j = 0; j < 8; ++j) { A[j] = 1.0f; B[j] = 0.0f; }

    const int s0 = chk * CHKLEN;
#pragma unroll 2
    for (int s = s0; s < s0 + CHKLEN; ++s) {
        const size_t row = (size_t)(s * BATCH + bb) * 384;
        uint4 zq = act8[row + dh];
        uint4 fq = act8[row + 128 + dh];
        const __half2* zp = (const __half2*)&zq;
        const __half2* fp = (const __half2*)&fq;
#pragma unroll
        for (int p = 0; p < 4; ++p) {
            float2 z2 = __half22float2(zp[p]);
            float2 f2 = __half22float2(fp[p]);
            A[2*p]   *= f2.x;
            A[2*p+1] *= f2.y;
            B[2*p]   = fmaf(f2.x, B[2*p]   - z2.x, z2.x);
            B[2*p+1] = fmaf(f2.y, B[2*p+1] - z2.y, z2.y);
        }
    }
    float* Adst = &g_A[(size_t)chk * (BATCH * DIM) + fc * 8];
    float* Bdst = &g_B[(size_t)chk * (BATCH * DIM) + fc * 8];
    *(float4*)(Adst)     = make_float4(A[0], A[1], A[2], A[3]);
    *(float4*)(Adst + 4) = make_float4(A[4], A[5], A[6], A[7]);
    *(float4*)(Bdst)     = make_float4(B[0], B[1], B[2], B[3]);
    *(float4*)(Bdst + 4) = make_float4(B[4], B[5], B[6], B[7]);
}

// ---------------------------------------------------------------------------
// Scan pass 2: compose chunk maps sequentially -> entry state h0 per chunk
// ---------------------------------------------------------------------------
__global__ __launch_bounds__(128)
void scan_part2(const float* __restrict__ hidden)
{
    const int fc = blockIdx.x * 128 + threadIdx.x;    // 0..4095
    float h[8];
    {
        float4 h0 = ((const float4*)hidden)[fc * 2];
        float4 h1 = ((const float4*)hidden)[fc * 2 + 1];
        h[0]=h0.x; h[1]=h0.y; h[2]=h0.z; h[3]=h0.w;
        h[4]=h1.x; h[5]=h1.y; h[6]=h1.z; h[7]=h1.w;
    }

#pragma unroll
    for (int c = 0; c < NCHK; ++c) {
        float* dst = &g_h0[(size_t)c * (BATCH * DIM) + fc * 8];
        *(float4*)(dst)     = make_float4(h[0], h[1], h[2], h[3]);
        *(float4*)(dst + 4) = make_float4(h[4], h[5], h[6], h[7]);
        const float* Ap = &g_A[(size_t)c * (BATCH * DIM) + fc * 8];
        const float* Bp = &g_B[(size_t)c * (BATCH * DIM) + fc * 8];
#pragma unroll
        for (int j = 0; j < 8; ++j)
            h[j] = fmaf(Ap[j], h[j], Bp[j]);
    }
}

// ---------------------------------------------------------------------------
// Scan pass 3: rerun recurrence per chunk from h0, write H = o*h (+ h_n)
// ---------------------------------------------------------------------------
__global__ __launch_bounds__(128)
void scan_part3(float* __restrict__ out)
{
    const int g   = blockIdx.x * 128 + threadIdx.x;
    const int chk = g >> 12;
    const int fc  = g & (NCH8 - 1);
    const int bb  = fc >> 7;
    const int dh  = fc & 127;

    const uint4* __restrict__ act8 = (const uint4*)g_act;
    float4* __restrict__ H4  = (float4*)out;
    float4* __restrict__ hn4 = (float4*)(out + (size_t)SEQ * BATCH * DIM);

    float h[8];
    {
        const float* src = &g_h0[(size_t)chk * (BATCH * DIM) + fc * 8];
        float4 a = *(const float4*)(src);
        float4 c = *(const float4*)(src + 4);
        h[0]=a.x; h[1]=a.y; h[2]=a.z; h[3]=a.w;
        h[4]=c.x; h[5]=c.y; h[6]=c.z; h[7]=c.w;
    }

    const int s0 = chk * CHKLEN;
#pragma unroll 2
    for (int s = s0; s < s0 + CHKLEN; ++s) {
        const size_t row = (size_t)(s * BATCH + bb) * 384;
        uint4 zq = act8[row + dh];
        uint4 fq = act8[row + 128 + dh];
        uint4 oq = act8[row + 256 + dh];
        const __half2* zp = (const __half2*)&zq;
        const __half2* fp = (const __half2*)&fq;
        const __half2* op = (const __half2*)&oq;
        float r[8];
#pragma unroll
        for (int p = 0; p < 4; ++p) {
            float2 z2 = __half22float2(zp[p]);
            float2 f2 = __half22float2(fp[p]);
            float2 o2 = __half22float2(op[p]);
            h[2*p]   = fmaf(f2.x, h[2*p]   - z2.x, z2.x);
            h[2*p+1] = fmaf(f2.y, h[2*p+1] - z2.y, z2.y);
            r[2*p]   = o2.x * h[2*p];
            r[2*p+1] = o2.y * h[2*p+1];
        }
        const size_t hbase = ((size_t)(s * BATCH + bb) * DIM + dh * 8) >> 2;
        H4[hbase]     = make_float4(r[0], r[1], r[2], r[3]);
        H4[hbase + 1] = make_float4(r[4], r[5], r[6], r[7]);
    }
    if (chk == NCHK - 1) {
        hn4[fc * 2]     = make_float4(h[0], h[1], h[2], h[3]);
        hn4[fc * 2 + 1] = make_float4(h[4], h[5], h[6], h[7]);
    }
}

// ---------------------------------------------------------------------------
extern "C" void kernel_launch(void* const* d_in, const int* in_sizes, int n_in,
                              void* d_out, int out_size)
{
    const float* X      = (const float*)d_in[0];   // [2048, 32, 1024]
    const float* hidden = (const float*)d_in[1];   // [1, 32, 1024]
    const float* W      = (const float*)d_in[2];   // [3072, 1024]
    const float* b      = (const float*)d_in[3];   // [3072]
    float* out = (float*)d_out;

    cudaFuncSetAttribute(gemm_hmma_kernel,
                         cudaFuncAttributeMaxDynamicSharedMemorySize,
                         SMEM_BYTES);

    dim3 grid(N_TOT / BN, M_TOT / BM);   // (24, 512)
    gemm_hmma_kernel<<<grid, 128, SMEM_BYTES>>>(X, W, b);

    scan_part1<<<(NCHK * NCH8) / 128, 128>>>();
    scan_part2<<<NCH8 / 128, 128>>>(hidden);
    scan_part3<<<(NCHK * NCH8) / 128, 128>>>(out);
}

// round 13
// speedup vs baseline: 1.0504x; 1.0504x over previous
#include <cuda_runtime.h>
#include <cuda_fp16.h>
#include <math.h>
#include <stdint.h>

// ---------------------------------------------------------------------------
// Problem dims (fixed by the reference)
// ---------------------------------------------------------------------------
#define SEQ    2048
#define BATCH  32
#define DIM    1024
#define M_TOT  (SEQ * BATCH)     // 65536
#define N_TOT  (3 * DIM)         // 3072
#define K_TOT  DIM               // 1024

// GEMM tile: 128-thread CTAs (4 warps, 64x64 warp tiles), 2 CTAs/SM
#define BM 128
#define BN 128
#define BK 32
#define NCHUNK (K_TOT / BK)      // 32
#define NSTAGE 3
#define ASTRIDE 36               // floats per SMEM row (32 + 4 pad): LDS banks
                                 // (36q + r)%32 = (4q+r)%32 all-distinct

// SMEM layout (bytes)
#define A_STG_BYTES (BM * ASTRIDE * 4)          // 18432
#define B_STG_BYTES (BN * ASTRIDE * 4)          // 18432
#define SMEM_B_BASE (NSTAGE * A_STG_BYTES)      // 55296
#define SMEM_BYTES  (SMEM_B_BASE + NSTAGE * B_STG_BYTES)  // 110592

// Scan chunking: 32 chunks of 64 steps; 8 features per thread (uint4 loads)
#define NCHK    32
#define CHKLEN  (SEQ / NCHK)      // 64
#define NCH8    (BATCH * DIM / 8) // 4096 chains-of-8

// Scratch (device globals; no cudaMalloc allowed)
__device__ __half g_act[(size_t)M_TOT * N_TOT];      // 384 MB fp16 gates
__device__ float  g_Xr[(size_t)M_TOT * K_TOT];       // 256 MB tf32-rounded X
__device__ float  g_Wr[(size_t)N_TOT * K_TOT];       // 12  MB tf32-rounded W
__device__ float  g_A [(size_t)NCHK * BATCH * DIM];  // per-chunk A = prod f
__device__ float  g_B [(size_t)NCHK * BATCH * DIM];  // per-chunk B
__device__ float  g_h0[(size_t)NCHK * BATCH * DIM];  // chunk entry states

// ---------------------------------------------------------------------------
// Helpers
// ---------------------------------------------------------------------------
__device__ __forceinline__ uint32_t smem_u32(const void* p) {
    uint32_t a;
    asm("{ .reg .u64 t; cvta.to.shared.u64 t, %1; cvt.u32.u64 %0, t; }"
        : "=r"(a) : "l"(p));
    return a;
}
__device__ __forceinline__ uint32_t tf32_rna(float x) {
    uint32_t r; asm("cvt.rna.tf32.f32 %0, %1;" : "=r"(r) : "f"(x)); return r;
}
__device__ __forceinline__ float rcp_fast(float x) {
    float r; asm("rcp.approx.f32 %0, %1;" : "=f"(r) : "f"(x)); return r;
}
__device__ __forceinline__ float sigmoid_f(float x) {
    return rcp_fast(1.0f + __expf(-x));
}
__device__ __forceinline__ float tanh_f(float x) {
    return 1.0f - 2.0f * rcp_fast(1.0f + __expf(2.0f * x));
}

__device__ __forceinline__ void cp_async16(uint32_t dst_smem, const void* src) {
    asm volatile("cp.async.cg.shared.global [%0], [%1], 16;"
                 :: "r"(dst_smem), "l"(src) : "memory");
}
__device__ __forceinline__ void cp_commit() {
    asm volatile("cp.async.commit_group;" ::: "memory");
}
template <int N>
__device__ __forceinline__ void cp_wait() {
    asm volatile("cp.async.wait_group %0;" :: "n"(N) : "memory");
}

// m16n8k8 tf32 HMMA (portable PTX, legal at compute_103)
__device__ __forceinline__ void mma_tf32(float* d,
                                         const uint32_t* a,
                                         const uint32_t* bb) {
    asm volatile(
        "mma.sync.aligned.m16n8k8.row.col.f32.tf32.tf32.f32 "
        "{%0,%1,%2,%3}, {%4,%5,%6,%7}, {%8,%9}, {%0,%1,%2,%3};\n"
        : "+f"(d[0]), "+f"(d[1]), "+f"(d[2]), "+f"(d[3])
        : "r"(a[0]), "r"(a[1]), "r"(a[2]), "r"(a[3]),
          "r"(bb[0]), "r"(bb[1]));
}

// ---------------------------------------------------------------------------
// Kernel 0: round fp32 -> tf32 (rna)
// ---------------------------------------------------------------------------
__global__ __launch_bounds__(256)
void round_tf32_kernel(const float* __restrict__ in, float* __restrict__ out, int n4)
{
    int i = blockIdx.x * blockDim.x + threadIdx.x;
    if (i >= n4) return;
    float4 v = ((const float4*)in)[i];
    float4 o;
    o.x = __uint_as_float(tf32_rna(v.x));
    o.y = __uint_as_float(tf32_rna(v.y));
    o.z = __uint_as_float(tf32_rna(v.z));
    o.w = __uint_as_float(tf32_rna(v.w));
    ((float4*)out)[i] = o;
}

// ---------------------------------------------------------------------------
// Kernel 1: cp.async 3-stage pipelined tf32 HMMA GEMM (R11 mainloop verbatim).
//   128 threads = 4 warps in 2(M) x 2(N); warp tile 64x64; 2 CTAs/SM.
//   Epilogue: bias + activation -> fp16 gates.
// ---------------------------------------------------------------------------
__global__ __launch_bounds__(128, 2)
void gemm_hmma_kernel(const float* __restrict__ b)
{
    extern __shared__ __align__(16) char smem[];
    const uint32_t sbase = smem_u32(smem);

    const int tid = threadIdx.x;
    const int wid = tid >> 5;       // 0..3
    const int lid = tid & 31;
    const int lq  = lid >> 2;       // 0..7
    const int lr  = lid & 3;        // 0..3

    const int wm = (wid >> 1) * 64; // warp M offset: 0 / 64
    const int wn = (wid & 1) * 64;  // warp N offset: 0 / 64

    const int block_m = blockIdx.y * BM;
    const int block_n = blockIdx.x * BN;

    const float* Abase = g_Xr + (size_t)block_m * K_TOT;
    const float* Bbase = g_Wr + (size_t)block_n * K_TOT;

    float acc[4][8][4];
#pragma unroll
    for (int mt = 0; mt < 4; ++mt)
#pragma unroll
        for (int nt = 0; nt < 8; ++nt)
#pragma unroll
            for (int r = 0; r < 4; ++r) acc[mt][nt][r] = 0.0f;

#pragma unroll
    for (int p = 0; p < NSTAGE; ++p) {
        const int kcol = p * BK;
        const uint32_t a_s = sbase + p * A_STG_BYTES;
        const uint32_t b_s = sbase + SMEM_B_BASE + p * B_STG_BYTES;
#pragma unroll
        for (int i = 0; i < 8; ++i) {
            int pos = tid + i * 128;
            int r = pos >> 3, c4 = pos & 7;
            cp_async16(a_s + (uint32_t)(r * ASTRIDE + c4 * 4) * 4,
                       Abase + (size_t)r * K_TOT + kcol + c4 * 4);
        }
#pragma unroll
        for (int i = 0; i < 8; ++i) {
            int pos = tid + i * 128;
            int r = pos >> 3, c4 = pos & 7;
            cp_async16(b_s + (uint32_t)(r * ASTRIDE + c4 * 4) * 4,
                       Bbase + (size_t)r * K_TOT + kcol + c4 * 4);
        }
        cp_commit();
    }

    for (int c = 0; c < NCHUNK; ++c) {
        const int buf = c % NSTAGE;
        cp_wait<NSTAGE - 1>();
        __syncthreads();

        const uint32_t* As = (const uint32_t*)(smem + buf * A_STG_BYTES);
        const uint32_t* Bs = (const uint32_t*)(smem + SMEM_B_BASE + buf * B_STG_BYTES);

#pragma unroll
        for (int ks = 0; ks < 4; ++ks) {
            const int k0 = ks * 8;
            uint32_t afrag[4][4], bfrag[8][2];
#pragma unroll
            for (int mt = 0; mt < 4; ++mt) {
                int base = (wm + mt * 16 + lq) * ASTRIDE + k0 + lr;
                afrag[mt][0] = As[base];
                afrag[mt][1] = As[base + 8 * ASTRIDE];
                afrag[mt][2] = As[base + 4];
                afrag[mt][3] = As[base + 8 * ASTRIDE + 4];
            }
#pragma unroll
            for (int nt = 0; nt < 8; ++nt) {
                int base = (wn + nt * 8 + lq) * ASTRIDE + k0 + lr;
                bfrag[nt][0] = Bs[base];
                bfrag[nt][1] = Bs[base + 4];
            }
#pragma unroll
            for (int mt = 0; mt < 4; ++mt)
#pragma unroll
                for (int nt = 0; nt < 8; ++nt)
                    mma_tf32(acc[mt][nt], afrag[mt], bfrag[nt]);
        }

        __syncthreads();

        if (c + NSTAGE < NCHUNK) {
            const int kcol = (c + NSTAGE) * BK;
            const uint32_t a_s = sbase + buf * A_STG_BYTES;
            const uint32_t b_s = sbase + SMEM_B_BASE + buf * B_STG_BYTES;
#pragma unroll
            for (int i = 0; i < 8; ++i) {
                int pos = tid + i * 128;
                int r = pos >> 3, c4 = pos & 7;
                cp_async16(a_s + (uint32_t)(r * ASTRIDE + c4 * 4) * 4,
                           Abase + (size_t)r * K_TOT + kcol + c4 * 4);
            }
#pragma unroll
            for (int i = 0; i < 8; ++i) {
                int pos = tid + i * 128;
                int r = pos >> 3, c4 = pos & 7;
                cp_async16(b_s + (uint32_t)(r * ASTRIDE + c4 * 4) * 4,
                           Bbase + (size_t)r * K_TOT + kcol + c4 * 4);
            }
        }
        cp_commit();
    }

    // ---- epilogue: bias + activation -> fp16 gates ----
    const bool is_tanh = (block_n < DIM);   // BN=128 divides DIM

#pragma unroll
    for (int nt = 0; nt < 8; ++nt) {
        const int gc = block_n + wn + nt * 8 + 2 * lr;   // even
        const float b0 = __ldg(&b[gc]);
        const float b1 = __ldg(&b[gc + 1]);
#pragma unroll
        for (int mt = 0; mt < 4; ++mt) {
            const int gm0 = block_m + wm + mt * 16 + lq;
            const int gm1 = gm0 + 8;
            float v00 = acc[mt][nt][0] + b0;
            float v01 = acc[mt][nt][1] + b1;
            float v10 = acc[mt][nt][2] + b0;
            float v11 = acc[mt][nt][3] + b1;
            float a00, a01, a10, a11;
            if (is_tanh) {
                a00 = tanh_f(v00); a01 = tanh_f(v01);
                a10 = tanh_f(v10); a11 = tanh_f(v11);
            } else {
                a00 = sigmoid_f(v00); a01 = sigmoid_f(v01);
                a10 = sigmoid_f(v10); a11 = sigmoid_f(v11);
            }
            *(__half2*)(&g_act[(size_t)gm0 * N_TOT + gc]) = __floats2half2_rn(a00, a01);
            *(__half2*)(&g_act[(size_t)gm1 * N_TOT + gc]) = __floats2half2_rn(a10, a11);
        }
    }
}

// ---------------------------------------------------------------------------
// Scan pass 1: per (chunk, 8-feature chain) affine map: h_out = A*h_in + B.
// 131072 threads (32 chunks x 4096 chains) -> ~7 warps/SM, bandwidth-bound.
// ---------------------------------------------------------------------------
__global__ __launch_bounds__(128)
void scan_part1(void)
{
    const int g   = blockIdx.x * 128 + threadIdx.x;   // 0 .. NCHK*NCH8-1
    const int chk = g >> 12;                          // /4096
    const int fc  = g & (NCH8 - 1);                   // chain-of-8 index
    const int bb  = fc >> 7;                          // batch
    const int dh  = fc & 127;                         // 8-feature group in DIM

    const uint4* __restrict__ act8 = (const uint4*)g_act;  // 8 halves per uint4

    float A[8], B[8];
#pragma unroll
    for (int j = 0; j < 8; ++j) { A[j] = 1.0f; B[j] = 0.0f; }

    const int s0 = chk * CHKLEN;
#pragma unroll 2
    for (int s = s0; s < s0 + CHKLEN; ++s) {
        const size_t row = (size_t)(s * BATCH + bb) * 384;
        uint4 zq = act8[row + dh];
        uint4 fq = act8[row + 128 + dh];
        const __half2* zp = (const __half2*)&zq;
        const __half2* fp = (const __half2*)&fq;
#pragma unroll
        for (int p = 0; p < 4; ++p) {
            float2 z2 = __half22float2(zp[p]);
            float2 f2 = __half22float2(fp[p]);
            A[2*p]   *= f2.x;
            A[2*p+1] *= f2.y;
            B[2*p]   = fmaf(f2.x, B[2*p]   - z2.x, z2.x);
            B[2*p+1] = fmaf(f2.y, B[2*p+1] - z2.y, z2.y);
        }
    }
    float* Adst = &g_A[(size_t)chk * (BATCH * DIM) + fc * 8];
    float* Bdst = &g_B[(size_t)chk * (BATCH * DIM) + fc * 8];
    *(float4*)(Adst)     = make_float4(A[0], A[1], A[2], A[3]);
    *(float4*)(Adst + 4) = make_float4(A[4], A[5], A[6], A[7]);
    *(float4*)(Bdst)     = make_float4(B[0], B[1], B[2], B[3]);
    *(float4*)(Bdst + 4) = make_float4(B[4], B[5], B[6], B[7]);
}

// ---------------------------------------------------------------------------
// Scan pass 2: compose chunk maps sequentially -> entry state h0 per chunk
// ---------------------------------------------------------------------------
__global__ __launch_bounds__(128)
void scan_part2(const float* __restrict__ hidden)
{
    const int fc = blockIdx.x * 128 + threadIdx.x;    // 0..4095
    float h[8];
    {
        float4 h0 = ((const float4*)hidden)[fc * 2];
        float4 h1 = ((const float4*)hidden)[fc * 2 + 1];
        h[0]=h0.x; h[1]=h0.y; h[2]=h0.z; h[3]=h0.w;
        h[4]=h1.x; h[5]=h1.y; h[6]=h1.z; h[7]=h1.w;
    }

#pragma unroll
    for (int c = 0; c < NCHK; ++c) {
        float* dst = &g_h0[(size_t)c * (BATCH * DIM) + fc * 8];
        *(float4*)(dst)     = make_float4(h[0], h[1], h[2], h[3]);
        *(float4*)(dst + 4) = make_float4(h[4], h[5], h[6], h[7]);
        const float* Ap = &g_A[(size_t)c * (BATCH * DIM) + fc * 8];
        const float* Bp = &g_B[(size_t)c * (BATCH * DIM) + fc * 8];
#pragma unroll
        for (int j = 0; j < 8; ++j)
            h[j] = fmaf(Ap[j], h[j], Bp[j]);
    }
}

// ---------------------------------------------------------------------------
// Scan pass 3: rerun recurrence per chunk from h0, write H = o*h (+ h_n)
// ---------------------------------------------------------------------------
__global__ __launch_bounds__(128)
void scan_part3(float* __restrict__ out)
{
    const int g   = blockIdx.x * 128 + threadIdx.x;
    const int chk = g >> 12;
    const int fc  = g & (NCH8 - 1);
    const int bb  = fc >> 7;
    const int dh  = fc & 127;

    const uint4* __restrict__ act8 = (const uint4*)g_act;
    float4* __restrict__ H4  = (float4*)out;
    float4* __restrict__ hn4 = (float4*)(out + (size_t)SEQ * BATCH * DIM);

    float h[8];
    {
        const float* src = &g_h0[(size_t)chk * (BATCH * DIM) + fc * 8];
        float4 a = *(const float4*)(src);
        float4 c = *(const float4*)(src + 4);
        h[0]=a.x; h[1]=a.y; h[2]=a.z; h[3]=a.w;
        h[4]=c.x; h[5]=c.y; h[6]=c.z; h[7]=c.w;
    }

    const int s0 = chk * CHKLEN;
#pragma unroll 2
    for (int s = s0; s < s0 + CHKLEN; ++s) {
        const size_t row = (size_t)(s * BATCH + bb) * 384;
        uint4 zq = act8[row + dh];
        uint4 fq = act8[row + 128 + dh];
        uint4 oq = act8[row + 256 + dh];
        const __half2* zp = (const __half2*)&zq;
        const __half2* fp = (const __half2*)&fq;
        const __half2* op = (const __half2*)&oq;
        float r[8];
#pragma unroll
        for (int p = 0; p < 4; ++p) {
            float2 z2 = __half22float2(zp[p]);
            float2 f2 = __half22float2(fp[p]);
            float2 o2 = __half22float2(op[p]);
            h[2*p]   = fmaf(f2.x, h[2*p]   - z2.x, z2.x);
            h[2*p+1] = fmaf(f2.y, h[2*p+1] - z2.y, z2.y);
            r[2*p]   = o2.x * h[2*p];
            r[2*p+1] = o2.y * h[2*p+1];
        }
        const size_t hbase = ((size_t)(s * BATCH + bb) * DIM + dh * 8) >> 2;
        H4[hbase]     = make_float4(r[0], r[1], r[2], r[3]);
        H4[hbase + 1] = make_float4(r[4], r[5], r[6], r[7]);
    }
    if (chk == NCHK - 1) {
        hn4[fc * 2]     = make_float4(h[0], h[1], h[2], h[3]);
        hn4[fc * 2 + 1] = make_float4(h[4], h[5], h[6], h[7]);
    }
}

// ---------------------------------------------------------------------------
extern "C" void kernel_launch(void* const* d_in, const int* in_sizes, int n_in,
                              void* d_out, int out_size)
{
    const float* X      = (const float*)d_in[0];   // [2048, 32, 1024]
    const float* hidden = (const float*)d_in[1];   // [1, 32, 1024]
    const float* W      = (const float*)d_in[2];   // [3072, 1024]
    const float* b      = (const float*)d_in[3];   // [3072]
    float* out = (float*)d_out;

    cudaFuncSetAttribute(gemm_hmma_kernel,
                         cudaFuncAttributeMaxDynamicSharedMemorySize,
                         SMEM_BYTES);

    float* Xr; float* Wr;
    cudaGetSymbolAddress((void**)&Xr, g_Xr);
    cudaGetSymbolAddress((void**)&Wr, g_Wr);

    // round inputs to tf32 (rna)
    {
        int n4x = (M_TOT * K_TOT) / 4;
        round_tf32_kernel<<<n4x / 256, 256>>>(X, Xr, n4x);
        int n4w = (N_TOT * K_TOT) / 4;
        round_tf32_kernel<<<n4w / 256, 256>>>(W, Wr, n4w);
    }

    dim3 grid(N_TOT / BN, M_TOT / BM);   // (24, 512)
    gemm_hmma_kernel<<<grid, 128, SMEM_BYTES>>>(b);

    scan_part1<<<(NCHK * NCH8) / 128, 128>>>();
    scan_part2<<<NCH8 / 128, 128>>>(hidden);
    scan_part3<<<(NCHK * NCH8) / 128, 128>>>(out);
}

// round 14
// speedup vs baseline: 1.6287x; 1.5505x over previous
#include <cuda_runtime.h>
#include <cuda_fp16.h>
#include <math.h>
#include <stdint.h>

// ---------------------------------------------------------------------------
// Problem dims (fixed by the reference)
// ---------------------------------------------------------------------------
#define SEQ    2048
#define BATCH  32
#define DIM    1024
#define M_TOT  (SEQ * BATCH)     // 65536
#define N_TOT  (3 * DIM)         // 3072
#define K_TOT  DIM               // 1024

// GEMM tile: 128-thread CTAs (4 warps, 64x64 warp tiles), 2 CTAs/SM, fp16 MMA
#define BM 128
#define BN 128
#define BK 32                    // fp16 elements per chunk (64 B/row)
#define NCHUNK (K_TOT / BK)      // 32
#define NSTAGE 4
#define HSTRIDE 20               // 32-bit words per SMEM row (16 data + 4 pad):
                                 // banks (20*lq + lr) % 32 all-distinct

// SMEM layout (bytes)
#define A_STG_BYTES (BM * HSTRIDE * 4)          // 10240
#define B_STG_BYTES (BN * HSTRIDE * 4)          // 10240
#define SMEM_B_BASE (NSTAGE * A_STG_BYTES)      // 40960
#define SMEM_BYTES  (SMEM_B_BASE + NSTAGE * B_STG_BYTES)  // 81920

// Scan chunking: 32 chunks of 64 steps; 8 features per thread (uint4 loads)
#define NCHK    32
#define CHKLEN  (SEQ / NCHK)      // 64
#define NCH8    (BATCH * DIM / 8) // 4096 chains-of-8

// Scratch (device globals; no cudaMalloc allowed)
__device__ __half g_act[(size_t)M_TOT * N_TOT];      // 384 MB fp16 gates
__device__ __half g_Xh[(size_t)M_TOT * K_TOT];       // 128 MB fp16 X
__device__ __half g_Wh[(size_t)N_TOT * K_TOT];       // 6   MB fp16 W
__device__ float  g_A [(size_t)NCHK * BATCH * DIM];  // per-chunk A = prod f
__device__ float  g_B [(size_t)NCHK * BATCH * DIM];  // per-chunk B
__device__ float  g_h0[(size_t)NCHK * BATCH * DIM];  // chunk entry states

// ---------------------------------------------------------------------------
// Helpers
// ---------------------------------------------------------------------------
__device__ __forceinline__ uint32_t smem_u32(const void* p) {
    uint32_t a;
    asm("{ .reg .u64 t; cvta.to.shared.u64 t, %1; cvt.u32.u64 %0, t; }"
        : "=r"(a) : "l"(p));
    return a;
}
__device__ __forceinline__ float rcp_fast(float x) {
    float r; asm("rcp.approx.f32 %0, %1;" : "=f"(r) : "f"(x)); return r;
}
__device__ __forceinline__ float sigmoid_f(float x) {
    return rcp_fast(1.0f + __expf(-x));
}
__device__ __forceinline__ float tanh_f(float x) {
    return 1.0f - 2.0f * rcp_fast(1.0f + __expf(2.0f * x));
}

__device__ __forceinline__ void cp_async16(uint32_t dst_smem, const void* src) {
    asm volatile("cp.async.cg.shared.global [%0], [%1], 16;"
                 :: "r"(dst_smem), "l"(src) : "memory");
}
__device__ __forceinline__ void cp_commit() {
    asm volatile("cp.async.commit_group;" ::: "memory");
}
template <int N>
__device__ __forceinline__ void cp_wait() {
    asm volatile("cp.async.wait_group %0;" :: "n"(N) : "memory");
}

// m16n8k16 fp16 HMMA, fp32 accumulate (portable PTX, legal at compute_103)
__device__ __forceinline__ void mma_f16(float* d,
                                        const uint32_t* a,
                                        const uint32_t* bb) {
    asm volatile(
        "mma.sync.aligned.m16n8k16.row.col.f32.f16.f16.f32 "
        "{%0,%1,%2,%3}, {%4,%5,%6,%7}, {%8,%9}, {%0,%1,%2,%3};\n"
        : "+f"(d[0]), "+f"(d[1]), "+f"(d[2]), "+f"(d[3])
        : "r"(a[0]), "r"(a[1]), "r"(a[2]), "r"(a[3]),
          "r"(bb[0]), "r"(bb[1]));
}

// ---------------------------------------------------------------------------
// Kernel 0: convert fp32 -> fp16 (rn); 8 floats per thread
// ---------------------------------------------------------------------------
__global__ __launch_bounds__(256)
void round_half_kernel(const float* __restrict__ in, __half* __restrict__ out, int n8)
{
    int i = blockIdx.x * blockDim.x + threadIdx.x;
    if (i >= n8) return;
    float4 v0 = ((const float4*)in)[i * 2];
    float4 v1 = ((const float4*)in)[i * 2 + 1];
    __half2 h0 = __floats2half2_rn(v0.x, v0.y);
    __half2 h1 = __floats2half2_rn(v0.z, v0.w);
    __half2 h2 = __floats2half2_rn(v1.x, v1.y);
    __half2 h3 = __floats2half2_rn(v1.z, v1.w);
    uint4 o;
    o.x = *(uint32_t*)&h0; o.y = *(uint32_t*)&h1;
    o.z = *(uint32_t*)&h2; o.w = *(uint32_t*)&h3;
    ((uint4*)out)[i] = o;
}

// ---------------------------------------------------------------------------
// Kernel 1: cp.async 4-stage pipelined fp16 HMMA GEMM (m16n8k16).
//   128 threads = 4 warps in 2(M) x 2(N); warp tile 64x64; 2 CTAs/SM.
//   Epilogue: bias + activation -> fp16 gates.
// ---------------------------------------------------------------------------
__global__ __launch_bounds__(128, 2)
void gemm_hmma_kernel(const float* __restrict__ b)
{
    extern __shared__ __align__(16) char smem[];
    const uint32_t sbase = smem_u32(smem);

    const int tid = threadIdx.x;
    const int wid = tid >> 5;       // 0..3
    const int lid = tid & 31;
    const int lq  = lid >> 2;       // 0..7
    const int lr  = lid & 3;        // 0..3

    const int wm = (wid >> 1) * 64; // warp M offset: 0 / 64
    const int wn = (wid & 1) * 64;  // warp N offset: 0 / 64

    const int block_m = blockIdx.y * BM;
    const int block_n = blockIdx.x * BN;

    const __half* Abase = g_Xh + (size_t)block_m * K_TOT;
    const __half* Bbase = g_Wh + (size_t)block_n * K_TOT;

    float acc[4][8][4];
#pragma unroll
    for (int mt = 0; mt < 4; ++mt)
#pragma unroll
        for (int nt = 0; nt < 8; ++nt)
#pragma unroll
            for (int r = 0; r < 4; ++r) acc[mt][nt][r] = 0.0f;

    // staging: tile = 128 rows x 64 B = 512 x 16B ops; 4 per thread per matrix
#pragma unroll
    for (int p = 0; p < NSTAGE; ++p) {
        const int kcol = p * BK;
        const uint32_t a_s = sbase + p * A_STG_BYTES;
        const uint32_t b_s = sbase + SMEM_B_BASE + p * B_STG_BYTES;
#pragma unroll
        for (int i = 0; i < 4; ++i) {
            int pos = tid + i * 128;
            int r = pos >> 2, c4 = pos & 3;
            cp_async16(a_s + (uint32_t)(r * 80 + c4 * 16),
                       Abase + (size_t)r * K_TOT + kcol + c4 * 8);
        }
#pragma unroll
        for (int i = 0; i < 4; ++i) {
            int pos = tid + i * 128;
            int r = pos >> 2, c4 = pos & 3;
            cp_async16(b_s + (uint32_t)(r * 80 + c4 * 16),
                       Bbase + (size_t)r * K_TOT + kcol + c4 * 8);
        }
        cp_commit();
    }

    for (int c = 0; c < NCHUNK; ++c) {
        const int buf = c % NSTAGE;
        cp_wait<NSTAGE - 1>();
        __syncthreads();

        const uint32_t* As = (const uint32_t*)(smem + buf * A_STG_BYTES);
        const uint32_t* Bs = (const uint32_t*)(smem + SMEM_B_BASE + buf * B_STG_BYTES);

        // 2 k-steps of 16 (BK=32)
#pragma unroll
        for (int ks = 0; ks < 2; ++ks) {
            const int kw = ks * 8;   // word offset within row (16 fp16 = 8 words)
            uint32_t afrag[4][4], bfrag[8][2];
#pragma unroll
            for (int mt = 0; mt < 4; ++mt) {
                int base = (wm + mt * 16 + lq) * HSTRIDE + kw + lr;
                afrag[mt][0] = As[base];
                afrag[mt][1] = As[base + 8 * HSTRIDE];
                afrag[mt][2] = As[base + 4];
                afrag[mt][3] = As[base + 8 * HSTRIDE + 4];
            }
#pragma unroll
            for (int nt = 0; nt < 8; ++nt) {
                int base = (wn + nt * 8 + lq) * HSTRIDE + kw + lr;
                bfrag[nt][0] = Bs[base];
                bfrag[nt][1] = Bs[base + 4];
            }
#pragma unroll
            for (int mt = 0; mt < 4; ++mt)
#pragma unroll
                for (int nt = 0; nt < 8; ++nt)
                    mma_f16(acc[mt][nt], afrag[mt], bfrag[nt]);
        }

        __syncthreads();

        if (c + NSTAGE < NCHUNK) {
            const int kcol = (c + NSTAGE) * BK;
            const uint32_t a_s = sbase + buf * A_STG_BYTES;
            const uint32_t b_s = sbase + SMEM_B_BASE + buf * B_STG_BYTES;
#pragma unroll
            for (int i = 0; i < 4; ++i) {
                int pos = tid + i * 128;
                int r = pos >> 2, c4 = pos & 3;
                cp_async16(a_s + (uint32_t)(r * 80 + c4 * 16),
                           Abase + (size_t)r * K_TOT + kcol + c4 * 8);
            }
#pragma unroll
            for (int i = 0; i < 4; ++i) {
                int pos = tid + i * 128;
                int r = pos >> 2, c4 = pos & 3;
                cp_async16(b_s + (uint32_t)(r * 80 + c4 * 16),
                           Bbase + (size_t)r * K_TOT + kcol + c4 * 8);
            }
        }
        cp_commit();   // keep group accounting uniform
    }

    // ---- epilogue: bias + activation -> fp16 gates ----
    const bool is_tanh = (block_n < DIM);   // BN=128 divides DIM

#pragma unroll
    for (int nt = 0; nt < 8; ++nt) {
        const int gc = block_n + wn + nt * 8 + 2 * lr;   // even
        const float b0 = __ldg(&b[gc]);
        const float b1 = __ldg(&b[gc + 1]);
#pragma unroll
        for (int mt = 0; mt < 4; ++mt) {
            const int gm0 = block_m + wm + mt * 16 + lq;
            const int gm1 = gm0 + 8;
            float v00 = acc[mt][nt][0] + b0;
            float v01 = acc[mt][nt][1] + b1;
            float v10 = acc[mt][nt][2] + b0;
            float v11 = acc[mt][nt][3] + b1;
            float a00, a01, a10, a11;
            if (is_tanh) {
                a00 = tanh_f(v00); a01 = tanh_f(v01);
                a10 = tanh_f(v10); a11 = tanh_f(v11);
            } else {
                a00 = sigmoid_f(v00); a01 = sigmoid_f(v01);
                a10 = sigmoid_f(v10); a11 = sigmoid_f(v11);
            }
            *(__half2*)(&g_act[(size_t)gm0 * N_TOT + gc]) = __floats2half2_rn(a00, a01);
            *(__half2*)(&g_act[(size_t)gm1 * N_TOT + gc]) = __floats2half2_rn(a10, a11);
        }
    }
}

// ---------------------------------------------------------------------------
// Scan pass 1: per (chunk, 8-feature chain) affine map: h_out = A*h_in + B.
// ---------------------------------------------------------------------------
__global__ __launch_bounds__(128)
void scan_part1(void)
{
    const int g   = blockIdx.x * 128 + threadIdx.x;   // 0 .. NCHK*NCH8-1
    const int chk = g >> 12;                          // /4096
    const int fc  = g & (NCH8 - 1);                   // chain-of-8 index
    const int bb  = fc >> 7;                          // batch
    const int dh  = fc & 127;                         // 8-feature group in DIM

    const uint4* __restrict__ act8 = (const uint4*)g_act;  // 8 halves per uint4

    float A[8], B[8];
#pragma unroll
    for (int j = 0; j < 8; ++j) { A[j] = 1.0f; B[j] = 0.0f; }

    const int s0 = chk * CHKLEN;
#pragma unroll 2
    for (int s = s0; s < s0 + CHKLEN; ++s) {
        const size_t row = (size_t)(s * BATCH + bb) * 384;
        uint4 zq = act8[row + dh];
        uint4 fq = act8[row + 128 + dh];
        const __half2* zp = (const __half2*)&zq;
        const __half2* fp = (const __half2*)&fq;
#pragma unroll
        for (int p = 0; p < 4; ++p) {
            float2 z2 = __half22float2(zp[p]);
            float2 f2 = __half22float2(fp[p]);
            A[2*p]   *= f2.x;
            A[2*p+1] *= f2.y;
            B[2*p]   = fmaf(f2.x, B[2*p]   - z2.x, z2.x);
            B[2*p+1] = fmaf(f2.y, B[2*p+1] - z2.y, z2.y);
        }
    }
    float* Adst = &g_A[(size_t)chk * (BATCH * DIM) + fc * 8];
    float* Bdst = &g_B[(size_t)chk * (BATCH * DIM) + fc * 8];
    *(float4*)(Adst)     = make_float4(A[0], A[1], A[2], A[3]);
    *(float4*)(Adst + 4) = make_float4(A[4], A[5], A[6], A[7]);
    *(float4*)(Bdst)     = make_float4(B[0], B[1], B[2], B[3]);
    *(float4*)(Bdst + 4) = make_float4(B[4], B[5], B[6], B[7]);
}

// ---------------------------------------------------------------------------
// Scan pass 2: compose chunk maps sequentially -> entry state h0 per chunk
// ---------------------------------------------------------------------------
__global__ __launch_bounds__(128)
void scan_part2(const float* __restrict__ hidden)
{
    const int fc = blockIdx.x * 128 + threadIdx.x;    // 0..4095
    float h[8];
    {
        float4 h0 = ((const float4*)hidden)[fc * 2];
        float4 h1 = ((const float4*)hidden)[fc * 2 + 1];
        h[0]=h0.x; h[1]=h0.y; h[2]=h0.z; h[3]=h0.w;
        h[4]=h1.x; h[5]=h1.y; h[6]=h1.z; h[7]=h1.w;
    }

#pragma unroll
    for (int c = 0; c < NCHK; ++c) {
        float* dst = &g_h0[(size_t)c * (BATCH * DIM) + fc * 8];
        *(float4*)(dst)     = make_float4(h[0], h[1], h[2], h[3]);
        *(float4*)(dst + 4) = make_float4(h[4], h[5], h[6], h[7]);
        const float* Ap = &g_A[(size_t)c * (BATCH * DIM) + fc * 8];
        const float* Bp = &g_B[(size_t)c * (BATCH * DIM) + fc * 8];
#pragma unroll
        for (int j = 0; j < 8; ++j)
            h[j] = fmaf(Ap[j], h[j], Bp[j]);
    }
}

// ---------------------------------------------------------------------------
// Scan pass 3: rerun recurrence per chunk from h0, write H = o*h (+ h_n)
// ---------------------------------------------------------------------------
__global__ __launch_bounds__(128)
void scan_part3(float* __restrict__ out)
{
    const int g   = blockIdx.x * 128 + threadIdx.x;
    const int chk = g >> 12;
    const int fc  = g & (NCH8 - 1);
    const int bb  = fc >> 7;
    const int dh  = fc & 127;

    const uint4* __restrict__ act8 = (const uint4*)g_act;
    float4* __restrict__ H4  = (float4*)out;
    float4* __restrict__ hn4 = (float4*)(out + (size_t)SEQ * BATCH * DIM);

    float h[8];
    {
        const float* src = &g_h0[(size_t)chk * (BATCH * DIM) + fc * 8];
        float4 a = *(const float4*)(src);
        float4 c = *(const float4*)(src + 4);
        h[0]=a.x; h[1]=a.y; h[2]=a.z; h[3]=a.w;
        h[4]=c.x; h[5]=c.y; h[6]=c.z; h[7]=c.w;
    }

    const int s0 = chk * CHKLEN;
#pragma unroll 2
    for (int s = s0; s < s0 + CHKLEN; ++s) {
        const size_t row = (size_t)(s * BATCH + bb) * 384;
        uint4 zq = act8[row + dh];
        uint4 fq = act8[row + 128 + dh];
        uint4 oq = act8[row + 256 + dh];
        const __half2* zp = (const __half2*)&zq;
        const __half2* fp = (const __half2*)&fq;
        const __half2* op = (const __half2*)&oq;
        float r[8];
#pragma unroll
        for (int p = 0; p < 4; ++p) {
            float2 z2 = __half22float2(zp[p]);
            float2 f2 = __half22float2(fp[p]);
            float2 o2 = __half22float2(op[p]);
            h[2*p]   = fmaf(f2.x, h[2*p]   - z2.x, z2.x);
            h[2*p+1] = fmaf(f2.y, h[2*p+1] - z2.y, z2.y);
            r[2*p]   = o2.x * h[2*p];
            r[2*p+1] = o2.y * h[2*p+1];
        }
        const size_t hbase = ((size_t)(s * BATCH + bb) * DIM + dh * 8) >> 2;
        H4[hbase]     = make_float4(r[0], r[1], r[2], r[3]);
        H4[hbase + 1] = make_float4(r[4], r[5], r[6], r[7]);
    }
    if (chk == NCHK - 1) {
        hn4[fc * 2]     = make_float4(h[0], h[1], h[2], h[3]);
        hn4[fc * 2 + 1] = make_float4(h[4], h[5], h[6], h[7]);
    }
}

// ---------------------------------------------------------------------------
extern "C" void kernel_launch(void* const* d_in, const int* in_sizes, int n_in,
                              void* d_out, int out_size)
{
    const float* X      = (const float*)d_in[0];   // [2048, 32, 1024]
    const float* hidden = (const float*)d_in[1];   // [1, 32, 1024]
    const float* W      = (const float*)d_in[2];   // [3072, 1024]
    const float* b      = (const float*)d_in[3];   // [3072]
    float* out = (float*)d_out;

    cudaFuncSetAttribute(gemm_hmma_kernel,
                         cudaFuncAttributeMaxDynamicSharedMemorySize,
                         SMEM_BYTES);

    __half* Xh; __half* Wh;
    cudaGetSymbolAddress((void**)&Xh, g_Xh);
    cudaGetSymbolAddress((void**)&Wh, g_Wh);

    // convert inputs to fp16 (rn)
    {
        int n8x = (M_TOT * K_TOT) / 8;   // 8388608
        round_half_kernel<<<n8x / 256, 256>>>(X, Xh, n8x);
        int n8w = (N_TOT * K_TOT) / 8;   // 393216
        round_half_kernel<<<n8w / 256, 256>>>(W, Wh, n8w);
    }

    dim3 grid(N_TOT / BN, M_TOT / BM);   // (24, 512)
    gemm_hmma_kernel<<<grid, 128, SMEM_BYTES>>>(b);

    scan_part1<<<(NCHK * NCH8) / 128, 128>>>();
    scan_part2<<<NCH8 / 128, 128>>>(hidden);
    scan_part3<<<(NCHK * NCH8) / 128, 128>>>(out);
}

// round 15
// speedup vs baseline: 1.9161x; 1.1764x over previous
#include <cuda_runtime.h>
#include <cuda_fp16.h>
#include <math.h>
#include <stdint.h>

// ---------------------------------------------------------------------------
// Problem dims (fixed by the reference)
// ---------------------------------------------------------------------------
#define SEQ    2048
#define BATCH  32
#define DIM    1024
#define M_TOT  (SEQ * BATCH)     // 65536
#define N_TOT  (3 * DIM)         // 3072
#define K_TOT  DIM               // 1024

// GEMM tile: 128-thread CTAs (4 warps, 64x64 warp tiles), 2 CTAs/SM, fp16 MMA
#define BM 128
#define BN 128
#define BK 64                    // fp16 elements per chunk (128 B/row)
#define NCHUNK (K_TOT / BK)      // 16
#define NSTAGE 3
#define HSTRIDE 36               // 32-bit words per SMEM row (32 data + 4 pad)
                                 // LDSM rows start at banks (4r mod 32): disjoint

// SMEM layout (bytes)
#define A_STG_BYTES (BM * HSTRIDE * 4)          // 18432
#define B_STG_BYTES (BN * HSTRIDE * 4)          // 18432
#define SMEM_B_BASE (NSTAGE * A_STG_BYTES)      // 55296
#define SMEM_BYTES  (SMEM_B_BASE + NSTAGE * B_STG_BYTES)  // 110592

// Scan chunking: 32 chunks of 64 steps; 8 features per thread (uint4 loads)
#define NCHK    32
#define CHKLEN  (SEQ / NCHK)      // 64
#define NCH8    (BATCH * DIM / 8) // 4096 chains-of-8

// Scratch (device globals; no cudaMalloc allowed)
__device__ __half g_act[(size_t)M_TOT * N_TOT];      // 384 MB fp16 gates
__device__ __half g_Xh[(size_t)M_TOT * K_TOT];       // 128 MB fp16 X
__device__ __half g_Wh[(size_t)N_TOT * K_TOT];       // 6   MB fp16 W
__device__ float  g_A [(size_t)NCHK * BATCH * DIM];  // per-chunk A = prod f
__device__ float  g_B [(size_t)NCHK * BATCH * DIM];  // per-chunk B
__device__ float  g_h0[(size_t)NCHK * BATCH * DIM];  // chunk entry states

// ---------------------------------------------------------------------------
// Helpers
// ---------------------------------------------------------------------------
__device__ __forceinline__ uint32_t smem_u32(const void* p) {
    uint32_t a;
    asm("{ .reg .u64 t; cvta.to.shared.u64 t, %1; cvt.u32.u64 %0, t; }"
        : "=r"(a) : "l"(p));
    return a;
}
__device__ __forceinline__ float rcp_fast(float x) {
    float r; asm("rcp.approx.f32 %0, %1;" : "=f"(r) : "f"(x)); return r;
}
__device__ __forceinline__ float sigmoid_f(float x) {
    return rcp_fast(1.0f + __expf(-x));
}
__device__ __forceinline__ float tanh_f(float x) {
    return 1.0f - 2.0f * rcp_fast(1.0f + __expf(2.0f * x));
}

__device__ __forceinline__ void cp_async16(uint32_t dst_smem, const void* src) {
    asm volatile("cp.async.cg.shared.global [%0], [%1], 16;"
                 :: "r"(dst_smem), "l"(src) : "memory");
}
__device__ __forceinline__ void cp_commit() {
    asm volatile("cp.async.commit_group;" ::: "memory");
}
template <int N>
__device__ __forceinline__ void cp_wait() {
    asm volatile("cp.async.wait_group %0;" :: "n"(N) : "memory");
}

// ldmatrix x4: four 8x8 b16 matrices, per-lane row addresses
__device__ __forceinline__ void ldsm_x4(uint32_t& r0, uint32_t& r1,
                                        uint32_t& r2, uint32_t& r3,
                                        uint32_t addr) {
    asm volatile(
        "ldmatrix.sync.aligned.m8n8.x4.shared.b16 {%0,%1,%2,%3}, [%4];"
        : "=r"(r0), "=r"(r1), "=r"(r2), "=r"(r3) : "r"(addr));
}

// m16n8k16 fp16 HMMA, fp32 accumulate (portable PTX, legal at compute_103)
__device__ __forceinline__ void mma_f16(float* d,
                                        const uint32_t* a,
                                        const uint32_t* bb) {
    asm volatile(
        "mma.sync.aligned.m16n8k16.row.col.f32.f16.f16.f32 "
        "{%0,%1,%2,%3}, {%4,%5,%6,%7}, {%8,%9}, {%0,%1,%2,%3};\n"
        : "+f"(d[0]), "+f"(d[1]), "+f"(d[2]), "+f"(d[3])
        : "r"(a[0]), "r"(a[1]), "r"(a[2]), "r"(a[3]),
          "r"(bb[0]), "r"(bb[1]));
}

// ---------------------------------------------------------------------------
// Kernel 0: convert fp32 -> fp16 (rn); 8 floats per thread
// ---------------------------------------------------------------------------
__global__ __launch_bounds__(256)
void round_half_kernel(const float* __restrict__ in, __half* __restrict__ out, int n8)
{
    int i = blockIdx.x * blockDim.x + threadIdx.x;
    if (i >= n8) return;
    float4 v0 = ((const float4*)in)[i * 2];
    float4 v1 = ((const float4*)in)[i * 2 + 1];
    __half2 h0 = __floats2half2_rn(v0.x, v0.y);
    __half2 h1 = __floats2half2_rn(v0.z, v0.w);
    __half2 h2 = __floats2half2_rn(v1.x, v1.y);
    __half2 h3 = __floats2half2_rn(v1.z, v1.w);
    uint4 o;
    o.x = *(uint32_t*)&h0; o.y = *(uint32_t*)&h1;
    o.z = *(uint32_t*)&h2; o.w = *(uint32_t*)&h3;
    ((uint4*)out)[i] = o;
}

// ---------------------------------------------------------------------------
// Kernel 1: cp.async 3-stage pipelined fp16 HMMA GEMM (m16n8k16 + ldmatrix).
//   128 threads = 4 warps in 2(M) x 2(N); warp tile 64x64; 2 CTAs/SM.
//   BK=64 (16 chunks -> half the syncs); fragments via ldmatrix.x4.
// ---------------------------------------------------------------------------
__global__ __launch_bounds__(128, 2)
void gemm_hmma_kernel(const float* __restrict__ b)
{
    extern __shared__ __align__(16) char smem[];
    const uint32_t sbase = smem_u32(smem);

    const int tid = threadIdx.x;
    const int wid = tid >> 5;       // 0..3
    const int lid = tid & 31;
    const int lq  = lid >> 2;       // 0..7
    const int lr  = lid & 3;        // 0..3

    const int wm = (wid >> 1) * 64; // warp M offset: 0 / 64
    const int wn = (wid & 1) * 64;  // warp N offset: 0 / 64

    const int block_m = blockIdx.y * BM;
    const int block_n = blockIdx.x * BN;

    const __half* Abase = g_Xh + (size_t)block_m * K_TOT;
    const __half* Bbase = g_Wh + (size_t)block_n * K_TOT;

    // per-lane ldmatrix offsets (in 32-bit words)
    // A x4 per mt: m0 rows 0-7 @kw, m1 rows 8-15 @kw, m2 rows 0-7 @kw+4, m3 rows 8-15 @kw+4
    const uint32_t aoff = (uint32_t)((wm + (lid & 15)) * HSTRIDE + ((lid >> 4) & 1) * 4);
    // B x4 per nt-pair: m0 n 0-7 @kw, m1 n 0-7 @kw+4, m2 n 8-15 @kw, m3 n 8-15 @kw+4
    const uint32_t boff = (uint32_t)((wn + ((lid >> 4) & 1) * 8 + (lid & 7)) * HSTRIDE
                                     + ((lid >> 3) & 1) * 4);

    float acc[4][8][4];
#pragma unroll
    for (int mt = 0; mt < 4; ++mt)
#pragma unroll
        for (int nt = 0; nt < 8; ++nt)
#pragma unroll
            for (int r = 0; r < 4; ++r) acc[mt][nt][r] = 0.0f;

    // staging: tile = 128 rows x 128 B = 1024 x 16B ops; 8 per thread per matrix
#pragma unroll
    for (int p = 0; p < NSTAGE; ++p) {
        const int kcol = p * BK;
        const uint32_t a_s = sbase + p * A_STG_BYTES;
        const uint32_t b_s = sbase + SMEM_B_BASE + p * B_STG_BYTES;
#pragma unroll
        for (int i = 0; i < 8; ++i) {
            int pos = tid + i * 128;
            int r = pos >> 3, c8 = pos & 7;
            cp_async16(a_s + (uint32_t)(r * (HSTRIDE * 4) + c8 * 16),
                       Abase + (size_t)r * K_TOT + kcol + c8 * 8);
        }
#pragma unroll
        for (int i = 0; i < 8; ++i) {
            int pos = tid + i * 128;
            int r = pos >> 3, c8 = pos & 7;
            cp_async16(b_s + (uint32_t)(r * (HSTRIDE * 4) + c8 * 16),
                       Bbase + (size_t)r * K_TOT + kcol + c8 * 8);
        }
        cp_commit();
    }

    for (int c = 0; c < NCHUNK; ++c) {
        const int buf = c % NSTAGE;
        cp_wait<NSTAGE - 1>();
        __syncthreads();

        const uint32_t abase = sbase + buf * A_STG_BYTES;
        const uint32_t bbase = sbase + SMEM_B_BASE + buf * B_STG_BYTES;

        // 4 k-steps of 16 (BK=64); kw = ks*8 words
#pragma unroll
        for (int ks = 0; ks < 4; ++ks) {
            const uint32_t kw = ks * 8;
            uint32_t afrag[4][4], bfrag[8][2];
#pragma unroll
            for (int mt = 0; mt < 4; ++mt) {
                uint32_t addr = abase + ((aoff + (uint32_t)(mt * 16 * HSTRIDE) + kw) << 2);
                ldsm_x4(afrag[mt][0], afrag[mt][1], afrag[mt][2], afrag[mt][3], addr);
            }
#pragma unroll
            for (int ntp = 0; ntp < 4; ++ntp) {
                uint32_t addr = bbase + ((boff + (uint32_t)(ntp * 16 * HSTRIDE) + kw) << 2);
                ldsm_x4(bfrag[2*ntp][0], bfrag[2*ntp][1],
                        bfrag[2*ntp+1][0], bfrag[2*ntp+1][1], addr);
            }
#pragma unroll
            for (int mt = 0; mt < 4; ++mt)
#pragma unroll
                for (int nt = 0; nt < 8; ++nt)
                    mma_f16(acc[mt][nt], afrag[mt], bfrag[nt]);
        }

        __syncthreads();

        if (c + NSTAGE < NCHUNK) {
            const int kcol = (c + NSTAGE) * BK;
            const uint32_t a_s = sbase + buf * A_STG_BYTES;
            const uint32_t b_s = sbase + SMEM_B_BASE + buf * B_STG_BYTES;
#pragma unroll
            for (int i = 0; i < 8; ++i) {
                int pos = tid + i * 128;
                int r = pos >> 3, c8 = pos & 7;
                cp_async16(a_s + (uint32_t)(r * (HSTRIDE * 4) + c8 * 16),
                           Abase + (size_t)r * K_TOT + kcol + c8 * 8);
            }
#pragma unroll
            for (int i = 0; i < 8; ++i) {
                int pos = tid + i * 128;
                int r = pos >> 3, c8 = pos & 7;
                cp_async16(b_s + (uint32_t)(r * (HSTRIDE * 4) + c8 * 16),
                           Bbase + (size_t)r * K_TOT + kcol + c8 * 8);
            }
        }
        cp_commit();   // keep group accounting uniform
    }

    // ---- epilogue: bias + activation -> fp16 gates ----
    const bool is_tanh = (block_n < DIM);   // BN=128 divides DIM

#pragma unroll
    for (int nt = 0; nt < 8; ++nt) {
        const int gc = block_n + wn + nt * 8 + 2 * lr;   // even
        const float b0 = __ldg(&b[gc]);
        const float b1 = __ldg(&b[gc + 1]);
#pragma unroll
        for (int mt = 0; mt < 4; ++mt) {
            const int gm0 = block_m + wm + mt * 16 + lq;
            const int gm1 = gm0 + 8;
            float v00 = acc[mt][nt][0] + b0;
            float v01 = acc[mt][nt][1] + b1;
            float v10 = acc[mt][nt][2] + b0;
            float v11 = acc[mt][nt][3] + b1;
            float a00, a01, a10, a11;
            if (is_tanh) {
                a00 = tanh_f(v00); a01 = tanh_f(v01);
                a10 = tanh_f(v10); a11 = tanh_f(v11);
            } else {
                a00 = sigmoid_f(v00); a01 = sigmoid_f(v01);
                a10 = sigmoid_f(v10); a11 = sigmoid_f(v11);
            }
            *(__half2*)(&g_act[(size_t)gm0 * N_TOT + gc]) = __floats2half2_rn(a00, a01);
            *(__half2*)(&g_act[(size_t)gm1 * N_TOT + gc]) = __floats2half2_rn(a10, a11);
        }
    }
}

// ---------------------------------------------------------------------------
// Scan pass 1: per (chunk, 8-feature chain) affine map: h_out = A*h_in + B.
// ---------------------------------------------------------------------------
__global__ __launch_bounds__(128)
void scan_part1(void)
{
    const int g   = blockIdx.x * 128 + threadIdx.x;   // 0 .. NCHK*NCH8-1
    const int chk = g >> 12;                          // /4096
    const int fc  = g & (NCH8 - 1);                   // chain-of-8 index
    const int bb  = fc >> 7;                          // batch
    const int dh  = fc & 127;                         // 8-feature group in DIM

    const uint4* __restrict__ act8 = (const uint4*)g_act;  // 8 halves per uint4

    float A[8], B[8];
#pragma unroll
    for (int j = 0; j < 8; ++j) { A[j] = 1.0f; B[j] = 0.0f; }

    const int s0 = chk * CHKLEN;
#pragma unroll 2
    for (int s = s0; s < s0 + CHKLEN; ++s) {
        const size_t row = (size_t)(s * BATCH + bb) * 384;
        uint4 zq = act8[row + dh];
        uint4 fq = act8[row + 128 + dh];
        const __half2* zp = (const __half2*)&zq;
        const __half2* fp = (const __half2*)&fq;
#pragma unroll
        for (int p = 0; p < 4; ++p) {
            float2 z2 = __half22float2(zp[p]);
            float2 f2 = __half22float2(fp[p]);
            A[2*p]   *= f2.x;
            A[2*p+1] *= f2.y;
            B[2*p]   = fmaf(f2.x, B[2*p]   - z2.x, z2.x);
            B[2*p+1] = fmaf(f2.y, B[2*p+1] - z2.y, z2.y);
        }
    }
    float* Adst = &g_A[(size_t)chk * (BATCH * DIM) + fc * 8];
    float* Bdst = &g_B[(size_t)chk * (BATCH * DIM) + fc * 8];
    *(float4*)(Adst)     = make_float4(A[0], A[1], A[2], A[3]);
    *(float4*)(Adst + 4) = make_float4(A[4], A[5], A[6], A[7]);
    *(float4*)(Bdst)     = make_float4(B[0], B[1], B[2], B[3]);
    *(float4*)(Bdst + 4) = make_float4(B[4], B[5], B[6], B[7]);
}

// ---------------------------------------------------------------------------
// Scan pass 2: compose chunk maps sequentially -> entry state h0 per chunk
// ---------------------------------------------------------------------------
__global__ __launch_bounds__(128)
void scan_part2(const float* __restrict__ hidden)
{
    const int fc = blockIdx.x * 128 + threadIdx.x;    // 0..4095
    float h[8];
    {
        float4 h0 = ((const float4*)hidden)[fc * 2];
        float4 h1 = ((const float4*)hidden)[fc * 2 + 1];
        h[0]=h0.x; h[1]=h0.y; h[2]=h0.z; h[3]=h0.w;
        h[4]=h1.x; h[5]=h1.y; h[6]=h1.z; h[7]=h1.w;
    }

#pragma unroll
    for (int c = 0; c < NCHK; ++c) {
        float* dst = &g_h0[(size_t)c * (BATCH * DIM) + fc * 8];
        *(float4*)(dst)     = make_float4(h[0], h[1], h[2], h[3]);
        *(float4*)(dst + 4) = make_float4(h[4], h[5], h[6], h[7]);
        const float* Ap = &g_A[(size_t)c * (BATCH * DIM) + fc * 8];
        const float* Bp = &g_B[(size_t)c * (BATCH * DIM) + fc * 8];
#pragma unroll
        for (int j = 0; j < 8; ++j)
            h[j] = fmaf(Ap[j], h[j], Bp[j]);
    }
}

// ---------------------------------------------------------------------------
// Scan pass 3: rerun recurrence per chunk from h0, write H = o*h (+ h_n)
// ---------------------------------------------------------------------------
__global__ __launch_bounds__(128)
void scan_part3(float* __restrict__ out)
{
    const int g   = blockIdx.x * 128 + threadIdx.x;
    const int chk = g >> 12;
    const int fc  = g & (NCH8 - 1);
    const int bb  = fc >> 7;
    const int dh  = fc & 127;

    const uint4* __restrict__ act8 = (const uint4*)g_act;
    float4* __restrict__ H4  = (float4*)out;
    float4* __restrict__ hn4 = (float4*)(out + (size_t)SEQ * BATCH * DIM);

    float h[8];
    {
        const float* src = &g_h0[(size_t)chk * (BATCH * DIM) + fc * 8];
        float4 a = *(const float4*)(src);
        float4 c = *(const float4*)(src + 4);
        h[0]=a.x; h[1]=a.y; h[2]=a.z; h[3]=a.w;
        h[4]=c.x; h[5]=c.y; h[6]=c.z; h[7]=c.w;
    }

    const int s0 = chk * CHKLEN;
#pragma unroll 2
    for (int s = s0; s < s0 + CHKLEN; ++s) {
        const size_t row = (size_t)(s * BATCH + bb) * 384;
        uint4 zq = act8[row + dh];
        uint4 fq = act8[row + 128 + dh];
        uint4 oq = act8[row + 256 + dh];
        const __half2* zp = (const __half2*)&zq;
        const __half2* fp = (const __half2*)&fq;
        const __half2* op = (const __half2*)&oq;
        float r[8];
#pragma unroll
        for (int p = 0; p < 4; ++p) {
            float2 z2 = __half22float2(zp[p]);
            float2 f2 = __half22float2(fp[p]);
            float2 o2 = __half22float2(op[p]);
            h[2*p]   = fmaf(f2.x, h[2*p]   - z2.x, z2.x);
            h[2*p+1] = fmaf(f2.y, h[2*p+1] - z2.y, z2.y);
            r[2*p]   = o2.x * h[2*p];
            r[2*p+1] = o2.y * h[2*p+1];
        }
        const size_t hbase = ((size_t)(s * BATCH + bb) * DIM + dh * 8) >> 2;
        H4[hbase]     = make_float4(r[0], r[1], r[2], r[3]);
        H4[hbase + 1] = make_float4(r[4], r[5], r[6], r[7]);
    }
    if (chk == NCHK - 1) {
        hn4[fc * 2]     = make_float4(h[0], h[1], h[2], h[3]);
        hn4[fc * 2 + 1] = make_float4(h[4], h[5], h[6], h[7]);
    }
}

// ---------------------------------------------------------------------------
extern "C" void kernel_launch(void* const* d_in, const int* in_sizes, int n_in,
                              void* d_out, int out_size)
{
    const float* X      = (const float*)d_in[0];   // [2048, 32, 1024]
    const float* hidden = (const float*)d_in[1];   // [1, 32, 1024]
    const float* W      = (const float*)d_in[2];   // [3072, 1024]
    const float* b      = (const float*)d_in[3];   // [3072]
    float* out = (float*)d_out;

    cudaFuncSetAttribute(gemm_hmma_kernel,
                         cudaFuncAttributeMaxDynamicSharedMemorySize,
                         SMEM_BYTES);

    __half* Xh; __half* Wh;
    cudaGetSymbolAddress((void**)&Xh, g_Xh);
    cudaGetSymbolAddress((void**)&Wh, g_Wh);

    // convert inputs to fp16 (rn)
    {
        int n8x = (M_TOT * K_TOT) / 8;   // 8388608
        round_half_kernel<<<n8x / 256, 256>>>(X, Xh, n8x);
        int n8w = (N_TOT * K_TOT) / 8;   // 393216
        round_half_kernel<<<n8w / 256, 256>>>(W, Wh, n8w);
    }

    dim3 grid(N_TOT / BN, M_TOT / BM);   // (24, 512)
    gemm_hmma_kernel<<<grid, 128, SMEM_BYTES>>>(b);

    scan_part1<<<(NCHK * NCH8) / 128, 128>>>();
    scan_part2<<<NCH8 / 128, 128>>>(hidden);
    scan_part3<<<(NCHK * NCH8) / 128, 128>>>(out);
}

// round 16
// speedup vs baseline: 2.0064x; 1.0471x over previous
#include <cuda_runtime.h>
#include <cuda_fp16.h>
#include <math.h>
#include <stdint.h>

// ---------------------------------------------------------------------------
// Problem dims (fixed by the reference)
// ---------------------------------------------------------------------------
#define SEQ    2048
#define BATCH  32
#define DIM    1024
#define M_TOT  (SEQ * BATCH)     // 65536
#define N_TOT  (3 * DIM)         // 3072
#define K_TOT  DIM               // 1024

// GEMM tile: 256-thread CTAs (8 warps 2Mx4N, warp tile 64x32), 2 CTAs/SM
#define BM 128
#define BN 128
#define BK 64                    // fp16 elements per chunk (128 B/row)
#define NCHUNK (K_TOT / BK)      // 16
#define NSTAGE 3
#define HSTRIDE 36               // 32-bit words per SMEM row (32 data + 4 pad)

// SMEM layout (bytes)
#define A_STG_BYTES (BM * HSTRIDE * 4)          // 18432
#define B_STG_BYTES (BN * HSTRIDE * 4)          // 18432
#define SMEM_B_BASE (NSTAGE * A_STG_BYTES)      // 55296
#define SMEM_BYTES  (SMEM_B_BASE + NSTAGE * B_STG_BYTES)  // 110592

// Scan chunking: 32 chunks of 64 steps; 8 features per thread (uint4 loads)
#define NCHK    32
#define CHKLEN  (SEQ / NCHK)      // 64
#define NCH8    (BATCH * DIM / 8) // 4096 chains-of-8

// Scratch (device globals; no cudaMalloc allowed)
__device__ __half g_act[(size_t)M_TOT * N_TOT];      // 384 MB fp16 gates
__device__ __half g_Xh[(size_t)M_TOT * K_TOT];       // 128 MB fp16 X
__device__ __half g_Wh[(size_t)N_TOT * K_TOT];       // 6   MB fp16 W
__device__ float  g_A [(size_t)NCHK * BATCH * DIM];  // per-chunk A = prod f
__device__ float  g_B [(size_t)NCHK * BATCH * DIM];  // per-chunk B
__device__ float  g_h0[(size_t)NCHK * BATCH * DIM];  // chunk entry states

// ---------------------------------------------------------------------------
// Helpers
// ---------------------------------------------------------------------------
__device__ __forceinline__ uint32_t smem_u32(const void* p) {
    uint32_t a;
    asm("{ .reg .u64 t; cvta.to.shared.u64 t, %1; cvt.u32.u64 %0, t; }"
        : "=r"(a) : "l"(p));
    return a;
}
__device__ __forceinline__ float rcp_fast(float x) {
    float r; asm("rcp.approx.f32 %0, %1;" : "=f"(r) : "f"(x)); return r;
}
__device__ __forceinline__ float sigmoid_f(float x) {
    return rcp_fast(1.0f + __expf(-x));
}
__device__ __forceinline__ float tanh_f(float x) {
    return 1.0f - 2.0f * rcp_fast(1.0f + __expf(2.0f * x));
}

__device__ __forceinline__ void cp_async16(uint32_t dst_smem, const void* src) {
    asm volatile("cp.async.cg.shared.global [%0], [%1], 16;"
                 :: "r"(dst_smem), "l"(src) : "memory");
}
__device__ __forceinline__ void cp_commit() {
    asm volatile("cp.async.commit_group;" ::: "memory");
}
template <int N>
__device__ __forceinline__ void cp_wait() {
    asm volatile("cp.async.wait_group %0;" :: "n"(N) : "memory");
}

// ldmatrix x4: four 8x8 b16 matrices, per-lane row addresses
__device__ __forceinline__ void ldsm_x4(uint32_t& r0, uint32_t& r1,
                                        uint32_t& r2, uint32_t& r3,
                                        uint32_t addr) {
    asm volatile(
        "ldmatrix.sync.aligned.m8n8.x4.shared.b16 {%0,%1,%2,%3}, [%4];"
        : "=r"(r0), "=r"(r1), "=r"(r2), "=r"(r3) : "r"(addr));
}

// m16n8k16 fp16 HMMA, fp32 accumulate (portable PTX, legal at compute_103)
__device__ __forceinline__ void mma_f16(float* d,
                                        const uint32_t* a,
                                        const uint32_t* bb) {
    asm volatile(
        "mma.sync.aligned.m16n8k16.row.col.f32.f16.f16.f32 "
        "{%0,%1,%2,%3}, {%4,%5,%6,%7}, {%8,%9}, {%0,%1,%2,%3};\n"
        : "+f"(d[0]), "+f"(d[1]), "+f"(d[2]), "+f"(d[3])
        : "r"(a[0]), "r"(a[1]), "r"(a[2]), "r"(a[3]),
          "r"(bb[0]), "r"(bb[1]));
}

// ---------------------------------------------------------------------------
// Kernel 0: convert fp32 -> fp16 (rn) for X and W in ONE launch
// ---------------------------------------------------------------------------
__global__ __launch_bounds__(256)
void round_half_kernel(const float* __restrict__ X, __half* __restrict__ Xh, int n8x,
                       const float* __restrict__ W, __half* __restrict__ Wh, int n8w)
{
    int i = blockIdx.x * blockDim.x + threadIdx.x;
    const float* in;
    __half* out;
    if (i < n8x) { in = X; out = Xh; }
    else if (i < n8x + n8w) { in = W; out = Wh; i -= n8x; }
    else return;
    float4 v0 = ((const float4*)in)[i * 2];
    float4 v1 = ((const float4*)in)[i * 2 + 1];
    __half2 h0 = __floats2half2_rn(v0.x, v0.y);
    __half2 h1 = __floats2half2_rn(v0.z, v0.w);
    __half2 h2 = __floats2half2_rn(v1.x, v1.y);
    __half2 h3 = __floats2half2_rn(v1.z, v1.w);
    uint4 o;
    o.x = *(uint32_t*)&h0; o.y = *(uint32_t*)&h1;
    o.z = *(uint32_t*)&h2; o.w = *(uint32_t*)&h3;
    ((uint4*)out)[i] = o;
}

// ---------------------------------------------------------------------------
// Kernel 1: cp.async 3-stage pipelined fp16 HMMA GEMM (m16n8k16 + ldmatrix).
//   256 threads = 8 warps in 2(M) x 4(N); warp tile 64x32; 2 CTAs/SM
//   -> 4 warps per SMSP to probe/break the per-warp HMMA issue limit.
// ---------------------------------------------------------------------------
__global__ __launch_bounds__(256, 2)
void gemm_hmma_kernel(const float* __restrict__ b)
{
    extern __shared__ __align__(16) char smem[];
    const uint32_t sbase = smem_u32(smem);

    const int tid = threadIdx.x;
    const int wid = tid >> 5;       // 0..7
    const int lid = tid & 31;
    const int lq  = lid >> 2;       // 0..7
    const int lr  = lid & 3;        // 0..3

    const int wm = (wid >> 2) * 64; // warp M offset: 0 / 64
    const int wn = (wid & 3) * 32;  // warp N offset: 0..96

    const int block_m = blockIdx.y * BM;
    const int block_n = blockIdx.x * BN;

    const __half* Abase = g_Xh + (size_t)block_m * K_TOT;
    const __half* Bbase = g_Wh + (size_t)block_n * K_TOT;

    // per-lane ldmatrix offsets (in 32-bit words)
    const uint32_t aoff = (uint32_t)((wm + (lid & 15)) * HSTRIDE + ((lid >> 4) & 1) * 4);
    const uint32_t boff = (uint32_t)((wn + ((lid >> 4) & 1) * 8 + (lid & 7)) * HSTRIDE
                                     + ((lid >> 3) & 1) * 4);

    float acc[4][4][4];
#pragma unroll
    for (int mt = 0; mt < 4; ++mt)
#pragma unroll
        for (int nt = 0; nt < 4; ++nt)
#pragma unroll
            for (int r = 0; r < 4; ++r) acc[mt][nt][r] = 0.0f;

    // staging: tile = 128 rows x 128 B = 1024 x 16B ops; 4 per thread per matrix
#pragma unroll
    for (int p = 0; p < NSTAGE; ++p) {
        const int kcol = p * BK;
        const uint32_t a_s = sbase + p * A_STG_BYTES;
        const uint32_t b_s = sbase + SMEM_B_BASE + p * B_STG_BYTES;
#pragma unroll
        for (int i = 0; i < 4; ++i) {
            int pos = tid + i * 256;
            int r = pos >> 3, c8 = pos & 7;
            cp_async16(a_s + (uint32_t)(r * (HSTRIDE * 4) + c8 * 16),
                       Abase + (size_t)r * K_TOT + kcol + c8 * 8);
        }
#pragma unroll
        for (int i = 0; i < 4; ++i) {
            int pos = tid + i * 256;
            int r = pos >> 3, c8 = pos & 7;
            cp_async16(b_s + (uint32_t)(r * (HSTRIDE * 4) + c8 * 16),
                       Bbase + (size_t)r * K_TOT + kcol + c8 * 8);
        }
        cp_commit();
    }

    for (int c = 0; c < NCHUNK; ++c) {
        const int buf = c % NSTAGE;
        cp_wait<NSTAGE - 1>();
        __syncthreads();

        const uint32_t abase = sbase + buf * A_STG_BYTES;
        const uint32_t bbase = sbase + SMEM_B_BASE + buf * B_STG_BYTES;

        // 4 k-steps of 16 (BK=64); kw = ks*8 words
#pragma unroll
        for (int ks = 0; ks < 4; ++ks) {
            const uint32_t kw = ks * 8;
            uint32_t afrag[4][4], bfrag[4][2];
#pragma unroll
            for (int mt = 0; mt < 4; ++mt) {
                uint32_t addr = abase + ((aoff + (uint32_t)(mt * 16 * HSTRIDE) + kw) << 2);
                ldsm_x4(afrag[mt][0], afrag[mt][1], afrag[mt][2], afrag[mt][3], addr);
            }
#pragma unroll
            for (int ntp = 0; ntp < 2; ++ntp) {
                uint32_t addr = bbase + ((boff + (uint32_t)(ntp * 16 * HSTRIDE) + kw) << 2);
                ldsm_x4(bfrag[2*ntp][0], bfrag[2*ntp][1],
                        bfrag[2*ntp+1][0], bfrag[2*ntp+1][1], addr);
            }
#pragma unroll
            for (int mt = 0; mt < 4; ++mt)
#pragma unroll
                for (int nt = 0; nt < 4; ++nt)
                    mma_f16(acc[mt][nt], afrag[mt], bfrag[nt]);
        }

        __syncthreads();

        if (c + NSTAGE < NCHUNK) {
            const int kcol = (c + NSTAGE) * BK;
            const uint32_t a_s = sbase + buf * A_STG_BYTES;
            const uint32_t b_s = sbase + SMEM_B_BASE + buf * B_STG_BYTES;
#pragma unroll
            for (int i = 0; i < 4; ++i) {
                int pos = tid + i * 256;
                int r = pos >> 3, c8 = pos & 7;
                cp_async16(a_s + (uint32_t)(r * (HSTRIDE * 4) + c8 * 16),
                           Abase + (size_t)r * K_TOT + kcol + c8 * 8);
            }
#pragma unroll
            for (int i = 0; i < 4; ++i) {
                int pos = tid + i * 256;
                int r = pos >> 3, c8 = pos & 7;
                cp_async16(b_s + (uint32_t)(r * (HSTRIDE * 4) + c8 * 16),
                           Bbase + (size_t)r * K_TOT + kcol + c8 * 8);
            }
        }
        cp_commit();   // keep group accounting uniform
    }

    // ---- epilogue: bias + activation -> fp16 gates ----
    const bool is_tanh = (block_n < DIM);   // BN=128 divides DIM

#pragma unroll
    for (int nt = 0; nt < 4; ++nt) {
        const int gc = block_n + wn + nt * 8 + 2 * lr;   // even
        const float b0 = __ldg(&b[gc]);
        const float b1 = __ldg(&b[gc + 1]);
#pragma unroll
        for (int mt = 0; mt < 4; ++mt) {
            const int gm0 = block_m + wm + mt * 16 + lq;
            const int gm1 = gm0 + 8;
            float v00 = acc[mt][nt][0] + b0;
            float v01 = acc[mt][nt][1] + b1;
            float v10 = acc[mt][nt][2] + b0;
            float v11 = acc[mt][nt][3] + b1;
            float a00, a01, a10, a11;
            if (is_tanh) {
                a00 = tanh_f(v00); a01 = tanh_f(v01);
                a10 = tanh_f(v10); a11 = tanh_f(v11);
            } else {
                a00 = sigmoid_f(v00); a01 = sigmoid_f(v01);
                a10 = sigmoid_f(v10); a11 = sigmoid_f(v11);
            }
            *(__half2*)(&g_act[(size_t)gm0 * N_TOT + gc]) = __floats2half2_rn(a00, a01);
            *(__half2*)(&g_act[(size_t)gm1 * N_TOT + gc]) = __floats2half2_rn(a10, a11);
        }
    }
}

// ---------------------------------------------------------------------------
// Scan pass 1: per (chunk, 8-feature chain) affine map: h_out = A*h_in + B.
// ---------------------------------------------------------------------------
__global__ __launch_bounds__(128)
void scan_part1(void)
{
    const int g   = blockIdx.x * 128 + threadIdx.x;   // 0 .. NCHK*NCH8-1
    const int chk = g >> 12;                          // /4096
    const int fc  = g & (NCH8 - 1);                   // chain-of-8 index
    const int bb  = fc >> 7;                          // batch
    const int dh  = fc & 127;                         // 8-feature group in DIM

    const uint4* __restrict__ act8 = (const uint4*)g_act;  // 8 halves per uint4

    float A[8], B[8];
#pragma unroll
    for (int j = 0; j < 8; ++j) { A[j] = 1.0f; B[j] = 0.0f; }

    const int s0 = chk * CHKLEN;
#pragma unroll 4
    for (int s = s0; s < s0 + CHKLEN; ++s) {
        const size_t row = (size_t)(s * BATCH + bb) * 384;
        uint4 zq = act8[row + dh];
        uint4 fq = act8[row + 128 + dh];
        const __half2* zp = (const __half2*)&zq;
        const __half2* fp = (const __half2*)&fq;
#pragma unroll
        for (int p = 0; p < 4; ++p) {
            float2 z2 = __half22float2(zp[p]);
            float2 f2 = __half22float2(fp[p]);
            A[2*p]   *= f2.x;
            A[2*p+1] *= f2.y;
            B[2*p]   = fmaf(f2.x, B[2*p]   - z2.x, z2.x);
            B[2*p+1] = fmaf(f2.y, B[2*p+1] - z2.y, z2.y);
        }
    }
    float* Adst = &g_A[(size_t)chk * (BATCH * DIM) + fc * 8];
    float* Bdst = &g_B[(size_t)chk * (BATCH * DIM) + fc * 8];
    *(float4*)(Adst)     = make_float4(A[0], A[1], A[2], A[3]);
    *(float4*)(Adst + 4) = make_float4(A[4], A[5], A[6], A[7]);
    *(float4*)(Bdst)     = make_float4(B[0], B[1], B[2], B[3]);
    *(float4*)(Bdst + 4) = make_float4(B[4], B[5], B[6], B[7]);
}

// ---------------------------------------------------------------------------
// Scan pass 2: compose chunk maps sequentially -> entry state h0 per chunk
// ---------------------------------------------------------------------------
__global__ __launch_bounds__(128)
void scan_part2(const float* __restrict__ hidden)
{
    const int fc = blockIdx.x * 128 + threadIdx.x;    // 0..4095
    float h[8];
    {
        float4 h0 = ((const float4*)hidden)[fc * 2];
        float4 h1 = ((const float4*)hidden)[fc * 2 + 1];
        h[0]=h0.x; h[1]=h0.y; h[2]=h0.z; h[3]=h0.w;
        h[4]=h1.x; h[5]=h1.y; h[6]=h1.z; h[7]=h1.w;
    }

#pragma unroll
    for (int c = 0; c < NCHK; ++c) {
        float* dst = &g_h0[(size_t)c * (BATCH * DIM) + fc * 8];
        *(float4*)(dst)     = make_float4(h[0], h[1], h[2], h[3]);
        *(float4*)(dst + 4) = make_float4(h[4], h[5], h[6], h[7]);
        const float* Ap = &g_A[(size_t)c * (BATCH * DIM) + fc * 8];
        const float* Bp = &g_B[(size_t)c * (BATCH * DIM) + fc * 8];
#pragma unroll
        for (int j = 0; j < 8; ++j)
            h[j] = fmaf(Ap[j], h[j], Bp[j]);
    }
}

// ---------------------------------------------------------------------------
// Scan pass 3: rerun recurrence per chunk from h0, write H = o*h (+ h_n)
// ---------------------------------------------------------------------------
__global__ __launch_bounds__(128)
void scan_part3(float* __restrict__ out)
{
    const int g   = blockIdx.x * 128 + threadIdx.x;
    const int chk = g >> 12;
    const int fc  = g & (NCH8 - 1);
    const int bb  = fc >> 7;
    const int dh  = fc & 127;

    const uint4* __restrict__ act8 = (const uint4*)g_act;
    float4* __restrict__ H4  = (float4*)out;
    float4* __restrict__ hn4 = (float4*)(out + (size_t)SEQ * BATCH * DIM);

    float h[8];
    {
        const float* src = &g_h0[(size_t)chk * (BATCH * DIM) + fc * 8];
        float4 a = *(const float4*)(src);
        float4 c = *(const float4*)(src + 4);
        h[0]=a.x; h[1]=a.y; h[2]=a.z; h[3]=a.w;
        h[4]=c.x; h[5]=c.y; h[6]=c.z; h[7]=c.w;
    }

    const int s0 = chk * CHKLEN;
#pragma unroll 4
    for (int s = s0; s < s0 + CHKLEN; ++s) {
        const size_t row = (size_t)(s * BATCH + bb) * 384;
        uint4 zq = act8[row + dh];
        uint4 fq = act8[row + 128 + dh];
        uint4 oq = act8[row + 256 + dh];
        const __half2* zp = (const __half2*)&zq;
        const __half2* fp = (const __half2*)&fq;
        const __half2* op = (const __half2*)&oq;
        float r[8];
#pragma unroll
        for (int p = 0; p < 4; ++p) {
            float2 z2 = __half22float2(zp[p]);
            float2 f2 = __half22float2(fp[p]);
            float2 o2 = __half22float2(op[p]);
            h[2*p]   = fmaf(f2.x, h[2*p]   - z2.x, z2.x);
            h[2*p+1] = fmaf(f2.y, h[2*p+1] - z2.y, z2.y);
            r[2*p]   = o2.x * h[2*p];
            r[2*p+1] = o2.y * h[2*p+1];
        }
        const size_t hbase = ((size_t)(s * BATCH + bb) * DIM + dh * 8) >> 2;
        H4[hbase]     = make_float4(r[0], r[1], r[2], r[3]);
        H4[hbase + 1] = make_float4(r[4], r[5], r[6], r[7]);
    }
    if (chk == NCHK - 1) {
        hn4[fc * 2]     = make_float4(h[0], h[1], h[2], h[3]);
        hn4[fc * 2 + 1] = make_float4(h[4], h[5], h[6], h[7]);
    }
}

// ---------------------------------------------------------------------------
extern "C" void kernel_launch(void* const* d_in, const int* in_sizes, int n_in,
                              void* d_out, int out_size)
{
    const float* X      = (const float*)d_in[0];   // [2048, 32, 1024]
    const float* hidden = (const float*)d_in[1];   // [1, 32, 1024]
    const float* W      = (const float*)d_in[2];   // [3072, 1024]
    const float* b      = (const float*)d_in[3];   // [3072]
    float* out = (float*)d_out;

    cudaFuncSetAttribute(gemm_hmma_kernel,
                         cudaFuncAttributeMaxDynamicSharedMemorySize,
                         SMEM_BYTES);

    __half* Xh; __half* Wh;
    cudaGetSymbolAddress((void**)&Xh, g_Xh);
    cudaGetSymbolAddress((void**)&Wh, g_Wh);

    // convert X and W to fp16 (rn) in one launch
    {
        int n8x = (M_TOT * K_TOT) / 8;   // 8388608
        int n8w = (N_TOT * K_TOT) / 8;   // 393216
        int total = n8x + n8w;
        round_half_kernel<<<(total + 255) / 256, 256>>>(X, Xh, n8x, W, Wh, n8w);
    }

    dim3 grid(N_TOT / BN, M_TOT / BM);   // (24, 512)
    gemm_hmma_kernel<<<grid, 256, SMEM_BYTES>>>(b);

    scan_part1<<<(NCHK * NCH8) / 128, 128>>>();
    scan_part2<<<NCH8 / 128, 128>>>(hidden);
    scan_part3<<<(NCHK * NCH8) / 128, 128>>>(out);
}

// round 17
// speedup vs baseline: 2.0171x; 1.0053x over previous
#include <cuda_runtime.h>
#include <cuda_fp16.h>
#include <math.h>
#include <stdint.h>

// ---------------------------------------------------------------------------
// Problem dims (fixed by the reference)
// ---------------------------------------------------------------------------
#define SEQ    2048
#define BATCH  32
#define DIM    1024
#define M_TOT  (SEQ * BATCH)     // 65536
#define N_TOT  (3 * DIM)         // 3072
#define K_TOT  DIM               // 1024

// GEMM tile: 256-thread CTAs (8 warps 2Mx4N, warp tile 64x32), 2 CTAs/SM
#define BM 128
#define BN 128
#define BK 64                    // fp16 elements per chunk (128 B/row)
#define NCHUNK (K_TOT / BK)      // 16
#define NSTAGE 3
#define HSTRIDE 36               // 32-bit words per SMEM row (32 data + 4 pad)

// SMEM layout (bytes)
#define A_STG_BYTES (BM * HSTRIDE * 4)          // 18432
#define B_STG_BYTES (BN * HSTRIDE * 4)          // 18432
#define SMEM_B_BASE (NSTAGE * A_STG_BYTES)      // 55296
#define SMEM_BYTES  (SMEM_B_BASE + NSTAGE * B_STG_BYTES)  // 110592

// Scan chunking: 32 chunks of 64 steps; 8 features per thread (uint4 loads)
#define NCHK    32
#define CHKLEN  (SEQ / NCHK)      // 64
#define NCH8    (BATCH * DIM / 8) // 4096 chains-of-8

// Scratch (device globals; no cudaMalloc allowed)
__device__ __half g_act[(size_t)M_TOT * N_TOT];      // 384 MB fp16 gates
__device__ __half g_Xh[(size_t)M_TOT * K_TOT];       // 128 MB fp16 X
__device__ __half g_Wh[(size_t)N_TOT * K_TOT];       // 6   MB fp16 W
__device__ float  g_A [(size_t)NCHK * BATCH * DIM];  // per-chunk A = prod f
__device__ float  g_B [(size_t)NCHK * BATCH * DIM];  // per-chunk B
__device__ float  g_h0[(size_t)NCHK * BATCH * DIM];  // chunk entry states

// ---------------------------------------------------------------------------
// Helpers
// ---------------------------------------------------------------------------
__device__ __forceinline__ uint32_t smem_u32(const void* p) {
    uint32_t a;
    asm("{ .reg .u64 t; cvta.to.shared.u64 t, %1; cvt.u32.u64 %0, t; }"
        : "=r"(a) : "l"(p));
    return a;
}
__device__ __forceinline__ float rcp_fast(float x) {
    float r; asm("rcp.approx.f32 %0, %1;" : "=f"(r) : "f"(x)); return r;
}
__device__ __forceinline__ float sigmoid_f(float x) {
    return rcp_fast(1.0f + __expf(-x));
}
__device__ __forceinline__ float tanh_f(float x) {
    return 1.0f - 2.0f * rcp_fast(1.0f + __expf(2.0f * x));
}

__device__ __forceinline__ void cp_async16(uint32_t dst_smem, const void* src) {
    asm volatile("cp.async.cg.shared.global [%0], [%1], 16;"
                 :: "r"(dst_smem), "l"(src) : "memory");
}
__device__ __forceinline__ void cp_commit() {
    asm volatile("cp.async.commit_group;" ::: "memory");
}
template <int N>
__device__ __forceinline__ void cp_wait() {
    asm volatile("cp.async.wait_group %0;" :: "n"(N) : "memory");
}

// ldmatrix x4: four 8x8 b16 matrices, per-lane row addresses
__device__ __forceinline__ void ldsm_x4(uint32_t& r0, uint32_t& r1,
                                        uint32_t& r2, uint32_t& r3,
                                        uint32_t addr) {
    asm volatile(
        "ldmatrix.sync.aligned.m8n8.x4.shared.b16 {%0,%1,%2,%3}, [%4];"
        : "=r"(r0), "=r"(r1), "=r"(r2), "=r"(r3) : "r"(addr));
}

// m16n8k16 fp16 HMMA, fp32 accumulate (portable PTX, legal at compute_103)
__device__ __forceinline__ void mma_f16(float* d,
                                        const uint32_t* a,
                                        const uint32_t* bb) {
    asm volatile(
        "mma.sync.aligned.m16n8k16.row.col.f32.f16.f16.f32 "
        "{%0,%1,%2,%3}, {%4,%5,%6,%7}, {%8,%9}, {%0,%1,%2,%3};\n"
        : "+f"(d[0]), "+f"(d[1]), "+f"(d[2]), "+f"(d[3])
        : "r"(a[0]), "r"(a[1]), "r"(a[2]), "r"(a[3]),
          "r"(bb[0]), "r"(bb[1]));
}

// ---------------------------------------------------------------------------
// Kernel 0: convert fp32 -> fp16 (rn) for X and W in ONE launch
// ---------------------------------------------------------------------------
__global__ __launch_bounds__(256)
void round_half_kernel(const float* __restrict__ X, __half* __restrict__ Xh, int n8x,
                       const float* __restrict__ W, __half* __restrict__ Wh, int n8w)
{
    int i = blockIdx.x * blockDim.x + threadIdx.x;
    const float* in;
    __half* out;
    if (i < n8x) { in = X; out = Xh; }
    else if (i < n8x + n8w) { in = W; out = Wh; i -= n8x; }
    else return;
    float4 v0 = ((const float4*)in)[i * 2];
    float4 v1 = ((const float4*)in)[i * 2 + 1];
    __half2 h0 = __floats2half2_rn(v0.x, v0.y);
    __half2 h1 = __floats2half2_rn(v0.z, v0.w);
    __half2 h2 = __floats2half2_rn(v1.x, v1.y);
    __half2 h3 = __floats2half2_rn(v1.z, v1.w);
    uint4 o;
    o.x = *(uint32_t*)&h0; o.y = *(uint32_t*)&h1;
    o.z = *(uint32_t*)&h2; o.w = *(uint32_t*)&h3;
    ((uint4*)out)[i] = o;
}

// ---------------------------------------------------------------------------
// Kernel 1: cp.async pipelined fp16 HMMA GEMM (m16n8k16 + ldmatrix).
//   256 threads = 8 warps in 2(M) x 4(N); warp tile 64x32; 2 CTAs/SM.
//   ONE barrier per chunk: wait -> bar -> refill (c+2 into the buffer freed
//   at c-1) -> MMA on chunk c.  2 cp.async groups in flight, 3 buffers.
// ---------------------------------------------------------------------------
__global__ __launch_bounds__(256, 2)
void gemm_hmma_kernel(const float* __restrict__ b)
{
    extern __shared__ __align__(16) char smem[];
    const uint32_t sbase = smem_u32(smem);

    const int tid = threadIdx.x;
    const int wid = tid >> 5;       // 0..7
    const int lid = tid & 31;
    const int lq  = lid >> 2;       // 0..7
    const int lr  = lid & 3;        // 0..3

    const int wm = (wid >> 2) * 64; // warp M offset: 0 / 64
    const int wn = (wid & 3) * 32;  // warp N offset: 0..96

    const int block_m = blockIdx.y * BM;
    const int block_n = blockIdx.x * BN;

    const __half* Abase = g_Xh + (size_t)block_m * K_TOT;
    const __half* Bbase = g_Wh + (size_t)block_n * K_TOT;

    // per-lane ldmatrix offsets (in 32-bit words)
    const uint32_t aoff = (uint32_t)((wm + (lid & 15)) * HSTRIDE + ((lid >> 4) & 1) * 4);
    const uint32_t boff = (uint32_t)((wn + ((lid >> 4) & 1) * 8 + (lid & 7)) * HSTRIDE
                                     + ((lid >> 3) & 1) * 4);

    float acc[4][4][4];
#pragma unroll
    for (int mt = 0; mt < 4; ++mt)
#pragma unroll
        for (int nt = 0; nt < 4; ++nt)
#pragma unroll
            for (int r = 0; r < 4; ++r) acc[mt][nt][r] = 0.0f;

    // ---- prologue: stage chunks 0 and 1 (2 groups in flight) ----
#pragma unroll
    for (int p = 0; p < 2; ++p) {
        const int kcol = p * BK;
        const uint32_t a_s = sbase + p * A_STG_BYTES;
        const uint32_t b_s = sbase + SMEM_B_BASE + p * B_STG_BYTES;
#pragma unroll
        for (int i = 0; i < 4; ++i) {
            int pos = tid + i * 256;
            int r = pos >> 3, c8 = pos & 7;
            cp_async16(a_s + (uint32_t)(r * (HSTRIDE * 4) + c8 * 16),
                       Abase + (size_t)r * K_TOT + kcol + c8 * 8);
        }
#pragma unroll
        for (int i = 0; i < 4; ++i) {
            int pos = tid + i * 256;
            int r = pos >> 3, c8 = pos & 7;
            cp_async16(b_s + (uint32_t)(r * (HSTRIDE * 4) + c8 * 16),
                       Bbase + (size_t)r * K_TOT + kcol + c8 * 8);
        }
        cp_commit();
    }

    for (int c = 0; c < NCHUNK; ++c) {
        const int buf = c % NSTAGE;
        cp_wait<1>();          // chunk c's group complete
        __syncthreads();       // all warps past chunk c-1's LDSMs

        // refill: chunk c+2 into buffer (c+2)%3 == (c-1)%3 (freed at c-1)
        if (c + 2 < NCHUNK) {
            const int kcol = (c + 2) * BK;
            const int nb = (c + 2) % NSTAGE;
            const uint32_t a_s = sbase + nb * A_STG_BYTES;
            const uint32_t b_s = sbase + SMEM_B_BASE + nb * B_STG_BYTES;
#pragma unroll
            for (int i = 0; i < 4; ++i) {
                int pos = tid + i * 256;
                int r = pos >> 3, c8 = pos & 7;
                cp_async16(a_s + (uint32_t)(r * (HSTRIDE * 4) + c8 * 16),
                           Abase + (size_t)r * K_TOT + kcol + c8 * 8);
            }
#pragma unroll
            for (int i = 0; i < 4; ++i) {
                int pos = tid + i * 256;
                int r = pos >> 3, c8 = pos & 7;
                cp_async16(b_s + (uint32_t)(r * (HSTRIDE * 4) + c8 * 16),
                           Bbase + (size_t)r * K_TOT + kcol + c8 * 8);
            }
        }
        cp_commit();           // uniform group accounting

        const uint32_t abase = sbase + buf * A_STG_BYTES;
        const uint32_t bbase = sbase + SMEM_B_BASE + buf * B_STG_BYTES;

        // 4 k-steps of 16 (BK=64); kw = ks*8 words
#pragma unroll
        for (int ks = 0; ks < 4; ++ks) {
            const uint32_t kw = ks * 8;
            uint32_t afrag[4][4], bfrag[4][2];
#pragma unroll
            for (int mt = 0; mt < 4; ++mt) {
                uint32_t addr = abase + ((aoff + (uint32_t)(mt * 16 * HSTRIDE) + kw) << 2);
                ldsm_x4(afrag[mt][0], afrag[mt][1], afrag[mt][2], afrag[mt][3], addr);
            }
#pragma unroll
            for (int ntp = 0; ntp < 2; ++ntp) {
                uint32_t addr = bbase + ((boff + (uint32_t)(ntp * 16 * HSTRIDE) + kw) << 2);
                ldsm_x4(bfrag[2*ntp][0], bfrag[2*ntp][1],
                        bfrag[2*ntp+1][0], bfrag[2*ntp+1][1], addr);
            }
#pragma unroll
            for (int mt = 0; mt < 4; ++mt)
#pragma unroll
                for (int nt = 0; nt < 4; ++nt)
                    mma_f16(acc[mt][nt], afrag[mt], bfrag[nt]);
        }
    }

    // ---- epilogue: bias + activation -> fp16 gates ----
    const bool is_tanh = (block_n < DIM);   // BN=128 divides DIM

#pragma unroll
    for (int nt = 0; nt < 4; ++nt) {
        const int gc = block_n + wn + nt * 8 + 2 * lr;   // even
        const float b0 = __ldg(&b[gc]);
        const float b1 = __ldg(&b[gc + 1]);
#pragma unroll
        for (int mt = 0; mt < 4; ++mt) {
            const int gm0 = block_m + wm + mt * 16 + lq;
            const int gm1 = gm0 + 8;
            float v00 = acc[mt][nt][0] + b0;
            float v01 = acc[mt][nt][1] + b1;
            float v10 = acc[mt][nt][2] + b0;
            float v11 = acc[mt][nt][3] + b1;
            float a00, a01, a10, a11;
            if (is_tanh) {
                a00 = tanh_f(v00); a01 = tanh_f(v01);
                a10 = tanh_f(v10); a11 = tanh_f(v11);
            } else {
                a00 = sigmoid_f(v00); a01 = sigmoid_f(v01);
                a10 = sigmoid_f(v10); a11 = sigmoid_f(v11);
            }
            *(__half2*)(&g_act[(size_t)gm0 * N_TOT + gc]) = __floats2half2_rn(a00, a01);
            *(__half2*)(&g_act[(size_t)gm1 * N_TOT + gc]) = __floats2half2_rn(a10, a11);
        }
    }
}

// ---------------------------------------------------------------------------
// Scan pass 1: per (chunk, 8-feature chain) affine map: h_out = A*h_in + B.
// ---------------------------------------------------------------------------
__global__ __launch_bounds__(128)
void scan_part1(void)
{
    const int g   = blockIdx.x * 128 + threadIdx.x;   // 0 .. NCHK*NCH8-1
    const int chk = g >> 12;                          // /4096
    const int fc  = g & (NCH8 - 1);                   // chain-of-8 index
    const int bb  = fc >> 7;                          // batch
    const int dh  = fc & 127;                         // 8-feature group in DIM

    const uint4* __restrict__ act8 = (const uint4*)g_act;  // 8 halves per uint4

    float A[8], B[8];
#pragma unroll
    for (int j = 0; j < 8; ++j) { A[j] = 1.0f; B[j] = 0.0f; }

    const int s0 = chk * CHKLEN;
#pragma unroll 4
    for (int s = s0; s < s0 + CHKLEN; ++s) {
        const size_t row = (size_t)(s * BATCH + bb) * 384;
        uint4 zq = act8[row + dh];
        uint4 fq = act8[row + 128 + dh];
        const __half2* zp = (const __half2*)&zq;
        const __half2* fp = (const __half2*)&fq;
#pragma unroll
        for (int p = 0; p < 4; ++p) {
            float2 z2 = __half22float2(zp[p]);
            float2 f2 = __half22float2(fp[p]);
            A[2*p]   *= f2.x;
            A[2*p+1] *= f2.y;
            B[2*p]   = fmaf(f2.x, B[2*p]   - z2.x, z2.x);
            B[2*p+1] = fmaf(f2.y, B[2*p+1] - z2.y, z2.y);
        }
    }
    float* Adst = &g_A[(size_t)chk * (BATCH * DIM) + fc * 8];
    float* Bdst = &g_B[(size_t)chk * (BATCH * DIM) + fc * 8];
    *(float4*)(Adst)     = make_float4(A[0], A[1], A[2], A[3]);
    *(float4*)(Adst + 4) = make_float4(A[4], A[5], A[6], A[7]);
    *(float4*)(Bdst)     = make_float4(B[0], B[1], B[2], B[3]);
    *(float4*)(Bdst + 4) = make_float4(B[4], B[5], B[6], B[7]);
}

// ---------------------------------------------------------------------------
// Scan pass 2: compose chunk maps -> entry state h0 per chunk.
// 32768 threads (1 feature each) for latency hiding; loads fully coalesced.
// ---------------------------------------------------------------------------
__global__ __launch_bounds__(128)
void scan_part2(const float* __restrict__ hidden)
{
    const int fc = blockIdx.x * 128 + threadIdx.x;    // 0..32767
    float h = hidden[fc];

#pragma unroll
    for (int c = 0; c < NCHK; ++c) {
        g_h0[(size_t)c * (BATCH * DIM) + fc] = h;
        const float A = g_A[(size_t)c * (BATCH * DIM) + fc];
        const float B = g_B[(size_t)c * (BATCH * DIM) + fc];
        h = fmaf(A, h, B);
    }
}

// ---------------------------------------------------------------------------
// Scan pass 3: rerun recurrence per chunk from h0, write H = o*h (+ h_n)
// ---------------------------------------------------------------------------
__global__ __launch_bounds__(128)
void scan_part3(float* __restrict__ out)
{
    const int g   = blockIdx.x * 128 + threadIdx.x;
    const int chk = g >> 12;
    const int fc  = g & (NCH8 - 1);
    const int bb  = fc >> 7;
    const int dh  = fc & 127;

    const uint4* __restrict__ act8 = (const uint4*)g_act;
    float4* __restrict__ H4  = (float4*)out;
    float4* __restrict__ hn4 = (float4*)(out + (size_t)SEQ * BATCH * DIM);

    float h[8];
    {
        const float* src = &g_h0[(size_t)chk * (BATCH * DIM) + fc * 8];
        float4 a = *(const float4*)(src);
        float4 c = *(const float4*)(src + 4);
        h[0]=a.x; h[1]=a.y; h[2]=a.z; h[3]=a.w;
        h[4]=c.x; h[5]=c.y; h[6]=c.z; h[7]=c.w;
    }

    const int s0 = chk * CHKLEN;
#pragma unroll 4
    for (int s = s0; s < s0 + CHKLEN; ++s) {
        const size_t row = (size_t)(s * BATCH + bb) * 384;
        uint4 zq = act8[row + dh];
        uint4 fq = act8[row + 128 + dh];
        uint4 oq = act8[row + 256 + dh];
        const __half2* zp = (const __half2*)&zq;
        const __half2* fp = (const __half2*)&fq;
        const __half2* op = (const __half2*)&oq;
        float r[8];
#pragma unroll
        for (int p = 0; p < 4; ++p) {
            float2 z2 = __half22float2(zp[p]);
            float2 f2 = __half22float2(fp[p]);
            float2 o2 = __half22float2(op[p]);
            h[2*p]   = fmaf(f2.x, h[2*p]   - z2.x, z2.x);
            h[2*p+1] = fmaf(f2.y, h[2*p+1] - z2.y, z2.y);
            r[2*p]   = o2.x * h[2*p];
            r[2*p+1] = o2.y * h[2*p+1];
        }
        const size_t hbase = ((size_t)(s * BATCH + bb) * DIM + dh * 8) >> 2;
        H4[hbase]     = make_float4(r[0], r[1], r[2], r[3]);
        H4[hbase + 1] = make_float4(r[4], r[5], r[6], r[7]);
    }
    if (chk == NCHK - 1) {
        hn4[fc * 2]     = make_float4(h[0], h[1], h[2], h[3]);
        hn4[fc * 2 + 1] = make_float4(h[4], h[5], h[6], h[7]);
    }
}

// ---------------------------------------------------------------------------
extern "C" void kernel_launch(void* const* d_in, const int* in_sizes, int n_in,
                              void* d_out, int out_size)
{
    const float* X      = (const float*)d_in[0];   // [2048, 32, 1024]
    const float* hidden = (const float*)d_in[1];   // [1, 32, 1024]
    const float* W      = (const float*)d_in[2];   // [3072, 1024]
    const float* b      = (const float*)d_in[3];   // [3072]
    float* out = (float*)d_out;

    cudaFuncSetAttribute(gemm_hmma_kernel,
                         cudaFuncAttributeMaxDynamicSharedMemorySize,
                         SMEM_BYTES);

    __half* Xh; __half* Wh;
    cudaGetSymbolAddress((void**)&Xh, g_Xh);
    cudaGetSymbolAddress((void**)&Wh, g_Wh);

    // convert X and W to fp16 (rn) in one launch
    {
        int n8x = (M_TOT * K_TOT) / 8;   // 8388608
        int n8w = (N_TOT * K_TOT) / 8;   // 393216
        int total = n8x + n8w;
        round_half_kernel<<<(total + 255) / 256, 256>>>(X, Xh, n8x, W, Wh, n8w);
    }

    dim3 grid(N_TOT / BN, M_TOT / BM);   // (24, 512)
    gemm_hmma_kernel<<<grid, 256, SMEM_BYTES>>>(b);

    scan_part1<<<(NCHK * NCH8) / 128, 128>>>();
    scan_part2<<<(BATCH * DIM) / 128, 128>>>(hidden);
    scan_part3<<<(NCHK * NCH8) / 128, 128>>>(out);
}